// round 1
// baseline (speedup 1.0000x reference)
#include <cuda_runtime.h>
#include <math.h>

#define NBATCH 32
#define C_ST_  2048
#define C_LT_  2048
#define LAT_   512
#define S_     512
#define L_     2048

// ---------------- scratch (allocation-free: __device__ globals) ----------------
__device__ float g_theta[(size_t)NBATCH * LAT_ * S_];   // (n, LAT, S)
__device__ float g_phi  [(size_t)NBATCH * LAT_ * L_];   // (n, LAT, L)
__device__ float g_gb   [(size_t)NBATCH * LAT_ * L_];   // (n, LAT, L)
__device__ float g_sc   [(size_t)NBATCH * S_   * L_];   // (n, S, L) scores -> probs
__device__ float g_attn [(size_t)NBATCH * LAT_ * S_];   // (n, LAT, S)
__device__ float g_norm [(size_t)NBATCH * LAT_ * S_];   // (n, LAT, S)
__device__ float g_stats[NBATCH * 2];                   // (mu, rstd) per batch

// ---------------- generic batched SGEMM: 128x128x8 tile, 8x8 per thread ----------------
// MODE 0 (NN): C[m,n] = sum_k A[m,k]*B[k,n]      (A: M x K lda, B: K x N ldb)
// MODE 1 (TN): C[m,n] = sum_k A[k,m]*B[k,n]      (A: K x M lda, B: K x N ldb)
// MODE 2 (NT): C[m,n] = sum_k A[m,k]*B[n,k]      (A: M x K lda, B: N x K ldb)
// C is M x N ldc. All of M, N divisible by 128 and K by 8 (guaranteed by shapes).
#define BM 128
#define BN 128
#define BK 8
#define TM 8
#define TN 8

template <int MODE>
__global__ __launch_bounds__(256)
void gemm_kernel(const float* __restrict__ Ag, const float* __restrict__ Bg,
                 float* __restrict__ Cg, const float* __restrict__ bias,
                 int K, int lda, int ldb, int ldc,
                 size_t strideA, size_t strideB, size_t strideC, float alpha)
{
    const float* A = Ag + (size_t)blockIdx.z * strideA;
    const float* B = Bg + (size_t)blockIdx.z * strideB;
    float*       C = Cg + (size_t)blockIdx.z * strideC;

    __shared__ float As[BK][BM];
    __shared__ float Bs[BK][BN];

    const int tid = threadIdx.x;
    const int tx  = tid & 15;   // 0..15 -> 8 output cols each
    const int ty  = tid >> 4;   // 0..15 -> 8 output rows each
    const int m0  = blockIdx.y * BM;
    const int n0  = blockIdx.x * BN;

    float acc[TM][TN];
#pragma unroll
    for (int i = 0; i < TM; i++)
#pragma unroll
        for (int j = 0; j < TN; j++) acc[i][j] = 0.f;

    for (int k0 = 0; k0 < K; k0 += BK) {
        // ---- load A tile -> As[k][m] ----
        if (MODE == 0 || MODE == 2) {
            // A[m,k] row-major: 128 rows x 8 k, each thread one float4 along k
            int idx = tid * 4;
            int am  = idx >> 3;     // 0..127
            int ak  = idx & 7;      // 0 or 4
            float4 v = *(const float4*)(A + (size_t)(m0 + am) * lda + k0 + ak);
            As[ak + 0][am] = v.x;
            As[ak + 1][am] = v.y;
            As[ak + 2][am] = v.z;
            As[ak + 3][am] = v.w;
        } else {
            // A[k,m]: contiguous in m
            int ak = tid >> 5;          // 0..7
            int am = (tid & 31) * 4;    // 0..124
            *(float4*)&As[ak][am] =
                *(const float4*)(A + (size_t)(k0 + ak) * lda + m0 + am);
        }
        // ---- load B tile -> Bs[k][n] ----
        if (MODE == 2) {
            // B[n,k] row-major: per thread one float4 along k
            int idx = tid * 4;
            int bn  = idx >> 3;
            int bk  = idx & 7;
            float4 v = *(const float4*)(B + (size_t)(n0 + bn) * ldb + k0 + bk);
            Bs[bk + 0][bn] = v.x;
            Bs[bk + 1][bn] = v.y;
            Bs[bk + 2][bn] = v.z;
            Bs[bk + 3][bn] = v.w;
        } else {
            // B[k,n]: contiguous in n
            int bk = tid >> 5;
            int bn = (tid & 31) * 4;
            *(float4*)&Bs[bk][bn] =
                *(const float4*)(B + (size_t)(k0 + bk) * ldb + n0 + bn);
        }
        __syncthreads();

#pragma unroll
        for (int kk = 0; kk < BK; kk++) {
            float a[TM], b[TN];
            *(float4*)&a[0] = *(const float4*)&As[kk][ty * TM];
            *(float4*)&a[4] = *(const float4*)&As[kk][ty * TM + 4];
            *(float4*)&b[0] = *(const float4*)&Bs[kk][tx * TN];
            *(float4*)&b[4] = *(const float4*)&Bs[kk][tx * TN + 4];
#pragma unroll
            for (int i = 0; i < TM; i++)
#pragma unroll
                for (int j = 0; j < TN; j++)
                    acc[i][j] = fmaf(a[i], b[j], acc[i][j]);
        }
        __syncthreads();
    }

#pragma unroll
    for (int i = 0; i < TM; i++) {
        int m = m0 + ty * TM + i;
        float bv = bias ? bias[m] : 0.f;
        float4 o0, o1;
        o0.x = fmaf(acc[i][0], alpha, bv);
        o0.y = fmaf(acc[i][1], alpha, bv);
        o0.z = fmaf(acc[i][2], alpha, bv);
        o0.w = fmaf(acc[i][3], alpha, bv);
        o1.x = fmaf(acc[i][4], alpha, bv);
        o1.y = fmaf(acc[i][5], alpha, bv);
        o1.z = fmaf(acc[i][6], alpha, bv);
        o1.w = fmaf(acc[i][7], alpha, bv);
        *(float4*)(C + (size_t)m * ldc + n0 + tx * TN)     = o0;
        *(float4*)(C + (size_t)m * ldc + n0 + tx * TN + 4) = o1;
    }
}

// ---------------- softmax over L=2048, one block (256 thr) per row ----------------
__global__ __launch_bounds__(256)
void softmax_kernel(float* __restrict__ sc)
{
    float* p = sc + (size_t)blockIdx.x * L_;
    const int tid = threadIdx.x;

    float v[8];
    float mx = -1e30f;
#pragma unroll
    for (int i = 0; i < 8; i++) {
        v[i] = p[tid + i * 256];
        mx = fmaxf(mx, v[i]);
    }
#pragma unroll
    for (int o = 16; o; o >>= 1) mx = fmaxf(mx, __shfl_xor_sync(0xffffffffu, mx, o));

    __shared__ float smax[8];
    __shared__ float ssum[8];
    if ((tid & 31) == 0) smax[tid >> 5] = mx;
    __syncthreads();
    float m2 = smax[0];
#pragma unroll
    for (int i = 1; i < 8; i++) m2 = fmaxf(m2, smax[i]);

    float s = 0.f;
#pragma unroll
    for (int i = 0; i < 8; i++) {
        v[i] = __expf(v[i] - m2);
        s += v[i];
    }
#pragma unroll
    for (int o = 16; o; o >>= 1) s += __shfl_xor_sync(0xffffffffu, s, o);
    if ((tid & 31) == 0) ssum[tid >> 5] = s;
    __syncthreads();
    float tot = 0.f;
#pragma unroll
    for (int i = 0; i < 8; i++) tot += ssum[i];

    float inv = 1.f / tot;
#pragma unroll
    for (int i = 0; i < 8; i++) p[tid + i * 256] = v[i] * inv;
}

// ---------------- layernorm stats: one block per batch over LAT*S elems ----------------
__global__ __launch_bounds__(512)
void ln_stats_kernel(const float* __restrict__ x, float* __restrict__ stats)
{
    const float* xb = x + (size_t)blockIdx.x * (LAT_ * S_);
    float s = 0.f, ss = 0.f;
    for (int i = threadIdx.x; i < LAT_ * S_; i += 512) {
        float v = xb[i];
        s += v;
        ss = fmaf(v, v, ss);
    }
#pragma unroll
    for (int o = 16; o; o >>= 1) {
        s  += __shfl_xor_sync(0xffffffffu, s, o);
        ss += __shfl_xor_sync(0xffffffffu, ss, o);
    }
    __shared__ float rs[16], rss[16];
    if ((threadIdx.x & 31) == 0) {
        rs[threadIdx.x >> 5]  = s;
        rss[threadIdx.x >> 5] = ss;
    }
    __syncthreads();
    if (threadIdx.x == 0) {
        float S = 0.f, SSq = 0.f;
#pragma unroll
        for (int i = 0; i < 16; i++) { S += rs[i]; SSq += rss[i]; }
        const float invN = 1.f / (float)(LAT_ * S_);
        float mu  = S * invN;
        float var = SSq * invN - mu * mu;
        stats[blockIdx.x * 2 + 0] = mu;
        stats[blockIdx.x * 2 + 1] = rsqrtf(var + 1e-5f);
    }
}

// ---------------- (x-mu)*rstd * ln_w + ln_b, relu ----------------
__global__ __launch_bounds__(256)
void norm_relu_kernel(const float* __restrict__ attn, const float* __restrict__ lnw,
                      const float* __restrict__ lnb, const float* __restrict__ stats,
                      float* __restrict__ out)
{
    size_t i4 = (size_t)blockIdx.x * blockDim.x + threadIdx.x;  // float4 index
    int n  = (int)(i4 >> 16);        // LAT*S/4 = 65536 float4 per batch
    int cs = (int)(i4 & 65535);
    float mu = stats[n * 2 + 0];
    float r  = stats[n * 2 + 1];
    float4 x = ((const float4*)attn)[i4];
    float4 w = ((const float4*)lnw)[cs];
    float4 b = ((const float4*)lnb)[cs];
    float4 y;
    y.x = fmaxf(fmaf((x.x - mu) * r, w.x, b.x), 0.f);
    y.y = fmaxf(fmaf((x.y - mu) * r, w.y, b.y), 0.f);
    y.z = fmaxf(fmaf((x.z - mu) * r, w.z, b.z), 0.f);
    y.w = fmaxf(fmaf((x.w - mu) * r, w.w, b.w), 0.f);
    ((float4*)out)[i4] = y;
}

// ---------------- launch ----------------
extern "C" void kernel_launch(void* const* d_in, const int* in_sizes, int n_in,
                              void* d_out, int out_size)
{
    const float* st    = (const float*)d_in[0];
    const float* lt    = (const float*)d_in[1];
    const float* w_st  = (const float*)d_in[2];
    const float* b_st  = (const float*)d_in[3];
    const float* w_lt  = (const float*)d_in[4];
    const float* b_lt  = (const float*)d_in[5];
    const float* w_g   = (const float*)d_in[6];
    const float* b_g   = (const float*)d_in[7];
    const float* ln_w  = (const float*)d_in[8];
    const float* ln_b  = (const float*)d_in[9];
    const float* w_out = (const float*)d_in[10];
    const float* b_out = (const float*)d_in[11];
    float* out = (float*)d_out;

    float *theta, *phi, *gb, *sc, *attn, *nrm, *stats;
    cudaGetSymbolAddress((void**)&theta, g_theta);
    cudaGetSymbolAddress((void**)&phi,   g_phi);
    cudaGetSymbolAddress((void**)&gb,    g_gb);
    cudaGetSymbolAddress((void**)&sc,    g_sc);
    cudaGetSymbolAddress((void**)&attn,  g_attn);
    cudaGetSymbolAddress((void**)&nrm,   g_norm);
    cudaGetSymbolAddress((void**)&stats, g_stats);

    const float inv_sqrt_lat = 0.044194173824159216f;  // 1/sqrt(512)

    // theta = w_st @ st  : M=LAT, N=S, K=C_ST
    gemm_kernel<0><<<dim3(S_ / BN, LAT_ / BM, NBATCH), 256>>>(
        w_st, st, theta, b_st, C_ST_, C_ST_, S_, S_,
        0, (size_t)C_ST_ * S_, (size_t)LAT_ * S_, 1.f);

    // phi = w_lt @ lt : M=LAT, N=L, K=C_LT
    gemm_kernel<0><<<dim3(L_ / BN, LAT_ / BM, NBATCH), 256>>>(
        w_lt, lt, phi, b_lt, C_LT_, C_LT_, L_, L_,
        0, (size_t)C_LT_ * L_, (size_t)LAT_ * L_, 1.f);

    // g = w_g @ lt
    gemm_kernel<0><<<dim3(L_ / BN, LAT_ / BM, NBATCH), 256>>>(
        w_g, lt, gb, b_g, C_LT_, C_LT_, L_, L_,
        0, (size_t)C_LT_ * L_, (size_t)LAT_ * L_, 1.f);

    // scores[s,l] = (1/sqrt(LAT)) * sum_c theta[c,s] phi[c,l] : TN, M=S, N=L, K=LAT
    gemm_kernel<1><<<dim3(L_ / BN, S_ / BM, NBATCH), 256>>>(
        theta, phi, sc, nullptr, LAT_, S_, L_, L_,
        (size_t)LAT_ * S_, (size_t)LAT_ * L_, (size_t)S_ * L_, inv_sqrt_lat);

    // softmax over L (in place)
    softmax_kernel<<<NBATCH * S_, 256>>>(sc);

    // attn[c,s] = sum_l g[c,l] p[s,l] : NT, M=LAT, N=S, K=L
    gemm_kernel<2><<<dim3(S_ / BN, LAT_ / BM, NBATCH), 256>>>(
        gb, sc, attn, nullptr, L_, L_, L_, S_,
        (size_t)LAT_ * L_, (size_t)S_ * L_, (size_t)LAT_ * S_, 1.f);

    // layernorm stats per batch
    ln_stats_kernel<<<NBATCH, 512>>>(attn, stats);

    // normalize + affine + relu
    norm_relu_kernel<<<(NBATCH * LAT_ * S_ / 4) / 256, 256>>>(attn, ln_w, ln_b, stats, nrm);

    // out = w_out @ nrm : M=C_ST, N=S, K=LAT
    gemm_kernel<0><<<dim3(S_ / BN, C_ST_ / BM, NBATCH), 256>>>(
        w_out, nrm, out, b_out, LAT_, LAT_, S_, S_,
        0, (size_t)LAT_ * S_, (size_t)C_ST_ * S_, 1.f);
}

// round 3
// speedup vs baseline: 3.7722x; 3.7722x over previous
#include <cuda_runtime.h>
#include <cstdint>
#include <math.h>

#define NBATCH 32
#define C_ST_  2048
#define C_LT_  2048
#define LAT_   512
#define S_     512
#define L_     2048

// ---------------- scratch (__device__ globals; no allocation) ----------------
__device__ float g_stT  [(size_t)NBATCH * S_ * C_ST_];    // (n, S, C_ST)  tf32-rounded
__device__ float g_ltT  [(size_t)NBATCH * L_ * C_LT_];    // (n, L, C_LT)  tf32-rounded
__device__ float g_thetaT[(size_t)NBATCH * S_ * LAT_];    // (n, S, LAT)   tf32-rounded
__device__ float g_phiT [(size_t)NBATCH * L_ * LAT_];     // (n, L, LAT)   tf32-rounded
__device__ float g_g    [(size_t)NBATCH * LAT_ * L_];     // (n, LAT, L)   tf32-rounded
__device__ float g_sc   [(size_t)NBATCH * S_ * L_];       // (n, S, L)
__device__ float g_attnT[(size_t)NBATCH * S_ * LAT_];     // (n, S, LAT)
__device__ float g_nrmT [(size_t)NBATCH * S_ * LAT_];     // (n, S, LAT)   tf32-rounded
__device__ float g_lnTw [(size_t)S_ * LAT_];
__device__ float g_lnTb [(size_t)S_ * LAT_];
__device__ float g_stats[NBATCH * 2];
__device__ float g_wstR [(size_t)LAT_ * C_ST_];           // tf32-rounded weights
__device__ float g_wltR [(size_t)LAT_ * C_LT_];
__device__ float g_wgR  [(size_t)LAT_ * C_LT_];
__device__ float g_woutR[(size_t)C_ST_ * LAT_];

// ---------------- helpers ----------------
__device__ __forceinline__ uint32_t smem_u32(const void* p) {
    uint32_t a;
    asm("{ .reg .u64 t; cvta.to.shared.u64 t, %1; cvt.u32.u64 %0, t; }" : "=r"(a) : "l"(p));
    return a;
}
__device__ __forceinline__ float to_tf32(float x) {
    float y;
    asm("cvt.rna.tf32.f32 %0, %1;" : "=f"(y) : "f"(x));
    return y;
}
#define CP_ASYNC16(dst, src) \
    asm volatile("cp.async.cg.shared.global [%0], [%1], 16;" :: "r"(dst), "l"(src))
#define CP_COMMIT() asm volatile("cp.async.commit_group;")
#define CP_WAIT1()  asm volatile("cp.async.wait_group 1;")

__device__ __forceinline__ uint32_t lds32(uint32_t addr) {
    uint32_t v;
    asm volatile("ld.shared.b32 %0, [%1];" : "=r"(v) : "r"(addr));
    return v;
}
__device__ __forceinline__ void mma_tf32(float* d, const uint32_t* a, const uint32_t* b) {
    asm volatile(
        "mma.sync.aligned.m16n8k8.row.col.f32.tf32.tf32.f32 "
        "{%0,%1,%2,%3},{%4,%5,%6,%7},{%8,%9},{%0,%1,%2,%3};"
        : "+f"(d[0]), "+f"(d[1]), "+f"(d[2]), "+f"(d[3])
        : "r"(a[0]), "r"(a[1]), "r"(a[2]), "r"(a[3]), "r"(b[0]), "r"(b[1]));
}

// ---------------- tf32 mma.sync GEMM: D[m][n] = alpha * sum_k A[m][k] B[n][k] (+bias) ----
// A: m rows, k contig (lda). B: n rows, k contig (ldb). C: m rows, n contig (ldc).
// Tile 128x128x32, 256 threads, 3-stage cp.async, XOR-swizzled smem.
#define NST 3
#define STAGE_BYTES 32768                 // A 16KB + B 16KB
#define GEMM_SMEM (NST * STAGE_BYTES)     // 96 KB

__global__ __launch_bounds__(256, 2)
void gemm_mma(const float* __restrict__ Ag, const float* __restrict__ Bg,
              float* __restrict__ Cg, const float* __restrict__ bias,
              int K, int lda, int ldb, int ldc,
              size_t sA, size_t sB, size_t sC, float alpha,
              int bias_mode, int round_out)
{
    extern __shared__ char smem[];
    const uint32_t sbase = smem_u32(smem);
    const int tid  = threadIdx.x;
    const int wid  = tid >> 5;
    const int lane = tid & 31;
    const int q    = lane >> 2;       // 0..7
    const int mq   = lane & 3;        // 0..3
    const int wm   = wid >> 2;        // 0..1 (m: 2 x 64)
    const int wn   = wid & 3;         // 0..3 (n: 4 x 32)
    const int m0   = blockIdx.y * 128;
    const int n0   = blockIdx.x * 128;

    const float* A = Ag + (size_t)blockIdx.z * sA + (size_t)m0 * lda;
    const float* B = Bg + (size_t)blockIdx.z * sB + (size_t)n0 * ldb;
    float*       C = Cg + (size_t)blockIdx.z * sC;

    // staging offsets: 4 chunks each for A and B per thread
    size_t   gAoff[4], gBoff[4];
    uint32_t sOff[4];
#pragma unroll
    for (int j = 0; j < 4; j++) {
        int id = tid + 256 * j;       // 0..1023
        int r  = id >> 3;             // 0..127
        int c4 = id & 7;              // 0..7
        gAoff[j] = (size_t)r * lda + c4 * 4;
        gBoff[j] = (size_t)r * ldb + c4 * 4;
        sOff[j]  = r * 128 + ((c4 ^ (r & 7)) << 4);
    }

    const int KT = K >> 5;

#define ISSUE(it_) do {                                                  \
        int s_ = (it_) % NST;                                            \
        uint32_t bA_ = sbase + s_ * STAGE_BYTES;                         \
        uint32_t bB_ = bA_ + 16384;                                      \
        int k0_ = (it_) << 5;                                            \
        _Pragma("unroll")                                                \
        for (int j = 0; j < 4; j++) {                                    \
            CP_ASYNC16(bA_ + sOff[j], A + gAoff[j] + k0_);               \
            CP_ASYNC16(bB_ + sOff[j], B + gBoff[j] + k0_);               \
        }                                                                \
    } while (0)

    ISSUE(0); CP_COMMIT();
    ISSUE(1); CP_COMMIT();

    float acc[4][4][4];
#pragma unroll
    for (int mi = 0; mi < 4; mi++)
#pragma unroll
        for (int ni = 0; ni < 4; ni++)
#pragma unroll
            for (int r = 0; r < 4; r++) acc[mi][ni][r] = 0.f;

    uint32_t aBase[4], bBase[4];
#pragma unroll
    for (int mi = 0; mi < 4; mi++) aBase[mi] = (wm * 64 + mi * 16 + q) * 128 + mq * 4;
#pragma unroll
    for (int ni = 0; ni < 4; ni++) bBase[ni] = (wn * 32 + ni * 8 + q) * 128 + mq * 4 + 16384;

    for (int it = 0; it < KT; ++it) {
        CP_WAIT1();
        __syncthreads();
        if (it + 2 < KT) ISSUE(it + 2);
        CP_COMMIT();

        const uint32_t buf = sbase + (it % NST) * STAGE_BYTES;
#pragma unroll
        for (int ki = 0; ki < 4; ki++) {
            const uint32_t c0 = (uint32_t)(((2 * ki) ^ q) << 4);
            const uint32_t c1 = (uint32_t)(((2 * ki + 1) ^ q) << 4);
            uint32_t a[4][4], b[4][2];
#pragma unroll
            for (int mi = 0; mi < 4; mi++) {
                uint32_t ad = buf + aBase[mi];
                a[mi][0] = lds32(ad + c0);
                a[mi][1] = lds32(ad + 1024 + c0);
                a[mi][2] = lds32(ad + c1);
                a[mi][3] = lds32(ad + 1024 + c1);
            }
#pragma unroll
            for (int ni = 0; ni < 4; ni++) {
                uint32_t bd = buf + bBase[ni];
                b[ni][0] = lds32(bd + c0);
                b[ni][1] = lds32(bd + c1);
            }
#pragma unroll
            for (int mi = 0; mi < 4; mi++)
#pragma unroll
                for (int ni = 0; ni < 4; ni++)
                    mma_tf32(acc[mi][ni], a[mi], b[ni]);
        }
    }
#undef ISSUE

    // ---------------- epilogue ----------------
#pragma unroll
    for (int mi = 0; mi < 4; mi++) {
        const int row = m0 + wm * 64 + mi * 16 + q;
        float bm0 = 0.f, bm8 = 0.f;
        if (bias_mode == 2) { bm0 = __ldg(bias + row); bm8 = __ldg(bias + row + 8); }
#pragma unroll
        for (int ni = 0; ni < 4; ni++) {
            const int col = n0 + wn * 32 + ni * 8 + 2 * mq;
            float bn0 = 0.f, bn1 = 0.f;
            if (bias_mode == 1) { bn0 = __ldg(bias + col); bn1 = __ldg(bias + col + 1); }
            float v00 = acc[mi][ni][0] * alpha;
            float v01 = acc[mi][ni][1] * alpha;
            float v10 = acc[mi][ni][2] * alpha;
            float v11 = acc[mi][ni][3] * alpha;
            if (bias_mode == 1) { v00 += bn0; v01 += bn1; v10 += bn0; v11 += bn1; }
            else if (bias_mode == 2) { v00 += bm0; v01 += bm0; v10 += bm8; v11 += bm8; }
            if (round_out) {
                v00 = to_tf32(v00); v01 = to_tf32(v01);
                v10 = to_tf32(v10); v11 = to_tf32(v11);
            }
            *(float2*)(C + (size_t)row * ldc + col)       = make_float2(v00, v01);
            *(float2*)(C + (size_t)(row + 8) * ldc + col) = make_float2(v10, v11);
        }
    }
}

// ---------------- transpose: in (z, R, C) -> out (z, C, R), optional tf32 round ----------
__global__ __launch_bounds__(256)
void transpose_kernel(const float* __restrict__ in, float* __restrict__ out,
                      int R, int C, int do_round)
{
    __shared__ float t[32][33];
    const float* ib = in  + (size_t)blockIdx.z * R * C;
    float*       ob = out + (size_t)blockIdx.z * R * C;
    int c = blockIdx.x * 32 + threadIdx.x;
#pragma unroll
    for (int i = 0; i < 4; i++) {
        int r = blockIdx.y * 32 + threadIdx.y + i * 8;
        t[threadIdx.y + i * 8][threadIdx.x] = ib[(size_t)r * C + c];
    }
    __syncthreads();
    int r2 = blockIdx.y * 32 + threadIdx.x;
#pragma unroll
    for (int i = 0; i < 4; i++) {
        int c2 = blockIdx.x * 32 + threadIdx.y + i * 8;
        float v = t[threadIdx.x][threadIdx.y + i * 8];
        if (do_round) v = to_tf32(v);
        ob[(size_t)c2 * R + r2] = v;
    }
}

// ---------------- elementwise tf32 round copy (for weights) ----------------
__global__ __launch_bounds__(256)
void round_copy_kernel(const float* __restrict__ in, float* __restrict__ out)
{
    size_t i = (size_t)blockIdx.x * blockDim.x + threadIdx.x;
    float4 v = ((const float4*)in)[i];
    v.x = to_tf32(v.x); v.y = to_tf32(v.y); v.z = to_tf32(v.z); v.w = to_tf32(v.w);
    ((float4*)out)[i] = v;
}

// ---------------- softmax over L=2048, one block per row; tf32-rounded output ----------
__global__ __launch_bounds__(256)
void softmax_kernel(float* __restrict__ sc)
{
    float* p = sc + (size_t)blockIdx.x * L_;
    const int tid = threadIdx.x;
    float v[8];
    float mx = -1e30f;
#pragma unroll
    for (int i = 0; i < 8; i++) { v[i] = p[tid + i * 256]; mx = fmaxf(mx, v[i]); }
#pragma unroll
    for (int o = 16; o; o >>= 1) mx = fmaxf(mx, __shfl_xor_sync(0xffffffffu, mx, o));
    __shared__ float smax[8], ssum[8];
    if ((tid & 31) == 0) smax[tid >> 5] = mx;
    __syncthreads();
    float m2 = smax[0];
#pragma unroll
    for (int i = 1; i < 8; i++) m2 = fmaxf(m2, smax[i]);
    float s = 0.f;
#pragma unroll
    for (int i = 0; i < 8; i++) { v[i] = __expf(v[i] - m2); s += v[i]; }
#pragma unroll
    for (int o = 16; o; o >>= 1) s += __shfl_xor_sync(0xffffffffu, s, o);
    if ((tid & 31) == 0) ssum[tid >> 5] = s;
    __syncthreads();
    float tot = 0.f;
#pragma unroll
    for (int i = 0; i < 8; i++) tot += ssum[i];
    float inv = 1.f / tot;
#pragma unroll
    for (int i = 0; i < 8; i++) p[tid + i * 256] = to_tf32(v[i] * inv);
}

// ---------------- layernorm stats: one block per batch ----------------
__global__ __launch_bounds__(512)
void ln_stats_kernel(const float* __restrict__ x, float* __restrict__ stats)
{
    const float* xb = x + (size_t)blockIdx.x * (LAT_ * S_);
    float s = 0.f, ss = 0.f;
    for (int i = threadIdx.x; i < LAT_ * S_; i += 512) {
        float v = xb[i];
        s += v;
        ss = fmaf(v, v, ss);
    }
#pragma unroll
    for (int o = 16; o; o >>= 1) {
        s  += __shfl_xor_sync(0xffffffffu, s, o);
        ss += __shfl_xor_sync(0xffffffffu, ss, o);
    }
    __shared__ float rs[16], rss[16];
    if ((threadIdx.x & 31) == 0) { rs[threadIdx.x >> 5] = s; rss[threadIdx.x >> 5] = ss; }
    __syncthreads();
    if (threadIdx.x == 0) {
        float S = 0.f, SSq = 0.f;
#pragma unroll
        for (int i = 0; i < 16; i++) { S += rs[i]; SSq += rss[i]; }
        const float invN = 1.f / (float)(LAT_ * S_);
        float mu  = S * invN;
        float var = SSq * invN - mu * mu;
        stats[blockIdx.x * 2 + 0] = mu;
        stats[blockIdx.x * 2 + 1] = rsqrtf(var + 1e-5f);
    }
}

// ---------------- normalize + affine + relu, tf32-rounded output ----------------
__global__ __launch_bounds__(256)
void norm_relu_kernel(const float* __restrict__ attn, const float* __restrict__ lnw,
                      const float* __restrict__ lnb, const float* __restrict__ stats,
                      float* __restrict__ out)
{
    size_t i4 = (size_t)blockIdx.x * blockDim.x + threadIdx.x;
    int n  = (int)(i4 >> 16);       // LAT*S/4 = 65536 float4 per batch
    int cs = (int)(i4 & 65535);
    float mu = stats[n * 2 + 0];
    float r  = stats[n * 2 + 1];
    float4 x = ((const float4*)attn)[i4];
    float4 w = ((const float4*)lnw)[cs];
    float4 b = ((const float4*)lnb)[cs];
    float4 y;
    y.x = to_tf32(fmaxf(fmaf((x.x - mu) * r, w.x, b.x), 0.f));
    y.y = to_tf32(fmaxf(fmaf((x.y - mu) * r, w.y, b.y), 0.f));
    y.z = to_tf32(fmaxf(fmaf((x.z - mu) * r, w.z, b.z), 0.f));
    y.w = to_tf32(fmaxf(fmaf((x.w - mu) * r, w.w, b.w), 0.f));
    ((float4*)out)[i4] = y;
}

// ---------------- launch ----------------
extern "C" void kernel_launch(void* const* d_in, const int* in_sizes, int n_in,
                              void* d_out, int out_size)
{
    const float* st    = (const float*)d_in[0];
    const float* lt    = (const float*)d_in[1];
    const float* w_st  = (const float*)d_in[2];
    const float* b_st  = (const float*)d_in[3];
    const float* w_lt  = (const float*)d_in[4];
    const float* b_lt  = (const float*)d_in[5];
    const float* w_g   = (const float*)d_in[6];
    const float* b_g   = (const float*)d_in[7];
    const float* ln_w  = (const float*)d_in[8];
    const float* ln_b  = (const float*)d_in[9];
    const float* w_out = (const float*)d_in[10];
    const float* b_out = (const float*)d_in[11];
    float* out = (float*)d_out;

    float *stT, *ltT, *thetaT, *phiT, *gb, *sc, *attnT, *nrmT, *lnTw, *lnTb, *stats;
    float *wstR, *wltR, *wgR, *woutR;
    cudaGetSymbolAddress((void**)&stT,    g_stT);
    cudaGetSymbolAddress((void**)&ltT,    g_ltT);
    cudaGetSymbolAddress((void**)&thetaT, g_thetaT);
    cudaGetSymbolAddress((void**)&phiT,   g_phiT);
    cudaGetSymbolAddress((void**)&gb,     g_g);
    cudaGetSymbolAddress((void**)&sc,     g_sc);
    cudaGetSymbolAddress((void**)&attnT,  g_attnT);
    cudaGetSymbolAddress((void**)&nrmT,   g_nrmT);
    cudaGetSymbolAddress((void**)&lnTw,   g_lnTw);
    cudaGetSymbolAddress((void**)&lnTb,   g_lnTb);
    cudaGetSymbolAddress((void**)&stats,  g_stats);
    cudaGetSymbolAddress((void**)&wstR,   g_wstR);
    cudaGetSymbolAddress((void**)&wltR,   g_wltR);
    cudaGetSymbolAddress((void**)&wgR,    g_wgR);
    cudaGetSymbolAddress((void**)&woutR,  g_woutR);

    cudaFuncSetAttribute(gemm_mma, cudaFuncAttributeMaxDynamicSharedMemorySize, GEMM_SMEM);

    const float inv_sqrt_lat = 0.044194173824159216f;   // 1/sqrt(512)
    dim3 tb(32, 8);

    // transposes (+tf32 rounding on data); weight rounding copies
    transpose_kernel<<<dim3(S_ / 32, C_ST_ / 32, NBATCH), tb>>>(st, stT, C_ST_, S_, 1);
    transpose_kernel<<<dim3(L_ / 32, C_LT_ / 32, NBATCH), tb>>>(lt, ltT, C_LT_, L_, 1);
    transpose_kernel<<<dim3(S_ / 32, LAT_ / 32, 1), tb>>>(ln_w, lnTw, LAT_, S_, 0);
    transpose_kernel<<<dim3(S_ / 32, LAT_ / 32, 1), tb>>>(ln_b, lnTb, LAT_, S_, 0);
    round_copy_kernel<<<(LAT_ * C_ST_ / 4) / 256, 256>>>(w_st, wstR);
    round_copy_kernel<<<(LAT_ * C_LT_ / 4) / 256, 256>>>(w_lt, wltR);
    round_copy_kernel<<<(LAT_ * C_LT_ / 4) / 256, 256>>>(w_g, wgR);
    round_copy_kernel<<<(C_ST_ * LAT_ / 4) / 256, 256>>>(w_out, woutR);

    // 1) thetaT[s][o] = sum_c stT[s][c] * w_st[o][c] + b_st[o]   (rounded)
    gemm_mma<<<dim3(LAT_ / 128, S_ / 128, NBATCH), 256, GEMM_SMEM>>>(
        stT, wstR, thetaT, b_st, C_ST_, C_ST_, C_ST_, LAT_,
        (size_t)S_ * C_ST_, 0, (size_t)S_ * LAT_, 1.f, 1, 1);

    // 2) phiT[l][o] = sum_c ltT[l][c] * w_lt[o][c] + b_lt[o]    (rounded)
    gemm_mma<<<dim3(LAT_ / 128, L_ / 128, NBATCH), 256, GEMM_SMEM>>>(
        ltT, wltR, phiT, b_lt, C_LT_, C_LT_, C_LT_, LAT_,
        (size_t)L_ * C_LT_, 0, (size_t)L_ * LAT_, 1.f, 1, 1);

    // 3) g[o][l] = sum_c w_g[o][c] * ltT[l][c] + b_g[o]         (rounded)
    gemm_mma<<<dim3(L_ / 128, LAT_ / 128, NBATCH), 256, GEMM_SMEM>>>(
        wgR, ltT, gb, b_g, C_LT_, C_LT_, C_LT_, L_,
        0, (size_t)L_ * C_LT_, (size_t)LAT_ * L_, 1.f, 2, 1);

    // 4) scores[s][l] = (1/sqrt(LAT)) * sum_c thetaT[s][c] * phiT[l][c]
    gemm_mma<<<dim3(L_ / 128, S_ / 128, NBATCH), 256, GEMM_SMEM>>>(
        thetaT, phiT, sc, nullptr, LAT_, LAT_, LAT_, L_,
        (size_t)S_ * LAT_, (size_t)L_ * LAT_, (size_t)S_ * L_, inv_sqrt_lat, 0, 0);

    // 5) softmax over L (in place, rounded output)
    softmax_kernel<<<NBATCH * S_, 256>>>(sc);

    // 6) attnT[s][c] = sum_l p[s][l] * g[c][l]
    gemm_mma<<<dim3(LAT_ / 128, S_ / 128, NBATCH), 256, GEMM_SMEM>>>(
        sc, gb, attnT, nullptr, L_, L_, L_, LAT_,
        (size_t)S_ * L_, (size_t)LAT_ * L_, (size_t)S_ * LAT_, 1.f, 0, 0);

    // 7) layernorm stats + normalize + relu (rounded output)
    ln_stats_kernel<<<NBATCH, 512>>>(attnT, stats);
    norm_relu_kernel<<<(NBATCH * LAT_ * S_ / 4) / 256, 256>>>(attnT, lnTw, lnTb, stats, nrmT);

    // 8) out[o][s] = sum_c w_out[o][c] * nrmT[s][c] + b_out[o]
    gemm_mma<<<dim3(S_ / 128, C_ST_ / 128, NBATCH), 256, GEMM_SMEM>>>(
        woutR, nrmT, out, b_out, LAT_, LAT_, LAT_, S_,
        0, (size_t)S_ * LAT_, (size_t)C_ST_ * S_, 1.f, 2, 0);
}

// round 7
// speedup vs baseline: 3.8283x; 1.0149x over previous
#include <cuda_runtime.h>
#include <cstdint>
#include <math.h>

#define NBATCH 32
#define C_ST_  2048
#define C_LT_  2048
#define LAT_   512
#define S_     512
#define L_     2048

// ---------------- scratch (__device__ globals; no allocation) ----------------
__device__ float g_thetaT[(size_t)NBATCH * S_ * LAT_];    // (n, S, LAT)   tf32-rounded
__device__ float g_phiT [(size_t)NBATCH * L_ * LAT_];     // (n, L, LAT)   tf32-rounded
__device__ float g_g    [(size_t)NBATCH * LAT_ * L_];     // (n, LAT, L)   tf32-rounded
__device__ float g_sc   [(size_t)NBATCH * S_ * L_];       // (n, S, L)
__device__ float g_attnT[(size_t)NBATCH * S_ * LAT_];     // (n, S, LAT)
__device__ float g_nrmT [(size_t)NBATCH * S_ * LAT_];     // (n, S, LAT)   tf32-rounded
__device__ float g_lnTw [(size_t)S_ * LAT_];
__device__ float g_lnTb [(size_t)S_ * LAT_];
__device__ float g_stats[NBATCH * 2];
__device__ float g_wstR [(size_t)LAT_ * C_ST_];           // tf32-rounded weights
__device__ float g_wltR [(size_t)LAT_ * C_LT_];
__device__ float g_wgR  [(size_t)LAT_ * C_LT_];
__device__ float g_woutR[(size_t)C_ST_ * LAT_];

// ---------------- helpers ----------------
__device__ __forceinline__ uint32_t smem_u32(const void* p) {
    uint32_t a;
    asm("{ .reg .u64 t; cvta.to.shared.u64 t, %1; cvt.u32.u64 %0, t; }" : "=r"(a) : "l"(p));
    return a;
}
__device__ __forceinline__ float to_tf32(float x) {
    float y;
    asm("cvt.rna.tf32.f32 %0, %1;" : "=f"(y) : "f"(x));
    return y;
}
__device__ __forceinline__ void cvt_frag(uint32_t& u) {
    float f = __uint_as_float(u);
    u = __float_as_uint(to_tf32(f));
}
#define CP_ASYNC16(dst, src) \
    asm volatile("cp.async.cg.shared.global [%0], [%1], 16;" :: "r"(dst), "l"(src))
#define CP_COMMIT() asm volatile("cp.async.commit_group;")
#define CP_WAIT1()  asm volatile("cp.async.wait_group 1;")

__device__ __forceinline__ uint32_t lds32(uint32_t addr) {
    uint32_t v;
    asm volatile("ld.shared.b32 %0, [%1];" : "=r"(v) : "r"(addr));
    return v;
}
__device__ __forceinline__ void mma_tf32(float* d, const uint32_t* a, const uint32_t* b) {
    asm volatile(
        "mma.sync.aligned.m16n8k8.row.col.f32.tf32.tf32.f32 "
        "{%0,%1,%2,%3},{%4,%5,%6,%7},{%8,%9},{%0,%1,%2,%3};"
        : "+f"(d[0]), "+f"(d[1]), "+f"(d[2]), "+f"(d[3])
        : "r"(a[0]), "r"(a[1]), "r"(a[2]), "r"(a[3]), "r"(b[0]), "r"(b[1]));
}

// ---------------- tf32 mma.sync GEMM: D[m][n] = alpha * sum_k A[m][k] B[n][k] (+bias) ----
// ATR=0: A stored [M][K] (m rows, k contig, lda = stride between m rows).
// ATR=1: A stored [K][M] (k rows, m contig, lda = stride between k rows).
// Same for B/BTR with n. RA/RB: apply cvt.rna.tf32 to fragments (raw fp32 inputs).
// Tile 128x128x32, 256 threads, 3-stage cp.async, swizzled smem.
#define NST 3
#define STAGE_BYTES 32768                 // A 16KB + B 16KB
#define GEMM_SMEM (NST * STAGE_BYTES)     // 96 KB

template <int ATR, int BTR, int RA, int RB>
__global__ __launch_bounds__(256, 2)
void gemm_mma(const float* __restrict__ Ag, const float* __restrict__ Bg,
              float* __restrict__ Cg, const float* __restrict__ bias,
              int K, int lda, int ldb, int ldc,
              size_t sA, size_t sB, size_t sC, float alpha,
              int bias_mode, int round_out)
{
    extern __shared__ char smem[];
    const uint32_t sbase = smem_u32(smem);
    const int tid  = threadIdx.x;
    const int wid  = tid >> 5;
    const int lane = tid & 31;
    const int q    = lane >> 2;       // 0..7
    const int mq   = lane & 3;        // 0..3
    const int wm   = wid >> 2;        // 0..1 (m: 2 x 64)
    const int wn   = wid & 3;         // 0..3 (n: 4 x 32)
    const int m0   = blockIdx.y * 128;
    const int n0   = blockIdx.x * 128;

    const float* A = Ag + (size_t)blockIdx.z * sA + (ATR ? (size_t)m0 : (size_t)m0 * lda);
    const float* B = Bg + (size_t)blockIdx.z * sB + (BTR ? (size_t)n0 : (size_t)n0 * ldb);
    float*       C = Cg + (size_t)blockIdx.z * sC;

    // staging offsets: 4 chunks each for A and B per thread
    size_t   gAoff[4], gBoff[4];
    uint32_t sAoff[4], sBoff[4];
#pragma unroll
    for (int j = 0; j < 4; j++) {
        int id = tid + 256 * j;       // 0..1023
        if (ATR) {
            int kr = id >> 5, c4 = id & 31;
            gAoff[j] = (size_t)kr * lda + c4 * 4;
            sAoff[j] = kr * 512 + ((c4 * 16) ^ ((kr & 3) << 5));
        } else {
            int r = id >> 3, c4 = id & 7;
            gAoff[j] = (size_t)r * lda + c4 * 4;
            sAoff[j] = r * 128 + ((c4 ^ (r & 7)) << 4);
        }
        if (BTR) {
            int kr = id >> 5, c4 = id & 31;
            gBoff[j] = (size_t)kr * ldb + c4 * 4;
            sBoff[j] = 16384 + kr * 512 + ((c4 * 16) ^ ((kr & 3) << 5));
        } else {
            int r = id >> 3, c4 = id & 7;
            gBoff[j] = (size_t)r * ldb + c4 * 4;
            sBoff[j] = 16384 + r * 128 + ((c4 ^ (r & 7)) << 4);
        }
    }
    const size_t aAdv = ATR ? (size_t)32 * lda : (size_t)32;
    const size_t bAdv = BTR ? (size_t)32 * ldb : (size_t)32;

    const int KT = K >> 5;

#define ISSUE(it_) do {                                                  \
        int s_ = (it_) % NST;                                            \
        uint32_t base_ = sbase + s_ * STAGE_BYTES;                       \
        const float* Ai_ = A + (size_t)(it_) * aAdv;                     \
        const float* Bi_ = B + (size_t)(it_) * bAdv;                     \
        _Pragma("unroll")                                                \
        for (int j = 0; j < 4; j++) {                                    \
            CP_ASYNC16(base_ + sAoff[j], Ai_ + gAoff[j]);                \
            CP_ASYNC16(base_ + sBoff[j], Bi_ + gBoff[j]);                \
        }                                                                \
    } while (0)

    ISSUE(0); CP_COMMIT();
    ISSUE(1); CP_COMMIT();

    float acc[4][4][4];
#pragma unroll
    for (int mi = 0; mi < 4; mi++)
#pragma unroll
        for (int ni = 0; ni < 4; ni++)
#pragma unroll
            for (int r = 0; r < 4; r++) acc[mi][ni][r] = 0.f;

    // fragment address bases
    uint32_t aBase[4], bBase[4];        // non-transposed mode
    uint32_t amLo[4], amHi[4];          // AT mode (byte offsets, swizzled)
    uint32_t bnLo[4];                   // BT mode
    const uint32_t swz = (uint32_t)(mq << 5);
#pragma unroll
    for (int mi = 0; mi < 4; mi++) {
        int m = wm * 64 + mi * 16 + q;
        aBase[mi] = m * 128 + mq * 4;
        amLo[mi]  = ((uint32_t)(m * 4)) ^ swz;
        amHi[mi]  = ((uint32_t)((m + 8) * 4)) ^ swz;
    }
#pragma unroll
    for (int ni = 0; ni < 4; ni++) {
        int n = wn * 32 + ni * 8 + q;
        bBase[ni] = n * 128 + mq * 4 + 16384;
        bnLo[ni]  = ((uint32_t)(n * 4)) ^ swz;
    }

    for (int it = 0; it < KT; ++it) {
        CP_WAIT1();
        __syncthreads();
        if (it + 2 < KT) ISSUE(it + 2);
        CP_COMMIT();

        const uint32_t buf = sbase + (it % NST) * STAGE_BYTES;
#pragma unroll
        for (int ki = 0; ki < 4; ki++) {
            uint32_t a[4][4], b[4][2];
            if (ATR) {
                const uint32_t kA = buf + ki * 4096 + mq * 512;
#pragma unroll
                for (int mi = 0; mi < 4; mi++) {
                    a[mi][0] = lds32(kA + amLo[mi]);
                    a[mi][1] = lds32(kA + amHi[mi]);
                    a[mi][2] = lds32(kA + 2048 + amLo[mi]);
                    a[mi][3] = lds32(kA + 2048 + amHi[mi]);
                }
            } else {
                const uint32_t c0 = (uint32_t)(((2 * ki) ^ q) << 4);
                const uint32_t c1 = (uint32_t)(((2 * ki + 1) ^ q) << 4);
#pragma unroll
                for (int mi = 0; mi < 4; mi++) {
                    uint32_t ad = buf + aBase[mi];
                    a[mi][0] = lds32(ad + c0);
                    a[mi][1] = lds32(ad + 1024 + c0);
                    a[mi][2] = lds32(ad + c1);
                    a[mi][3] = lds32(ad + 1024 + c1);
                }
            }
            if (BTR) {
                const uint32_t kB = buf + 16384 + ki * 4096 + mq * 512;
#pragma unroll
                for (int ni = 0; ni < 4; ni++) {
                    b[ni][0] = lds32(kB + bnLo[ni]);
                    b[ni][1] = lds32(kB + 2048 + bnLo[ni]);
                }
            } else {
                const uint32_t c0 = (uint32_t)(((2 * ki) ^ q) << 4);
                const uint32_t c1 = (uint32_t)(((2 * ki + 1) ^ q) << 4);
#pragma unroll
                for (int ni = 0; ni < 4; ni++) {
                    uint32_t bd = buf + bBase[ni];
                    b[ni][0] = lds32(bd + c0);
                    b[ni][1] = lds32(bd + c1);
                }
            }
            if (RA) {
#pragma unroll
                for (int mi = 0; mi < 4; mi++)
#pragma unroll
                    for (int r = 0; r < 4; r++) cvt_frag(a[mi][r]);
            }
            if (RB) {
#pragma unroll
                for (int ni = 0; ni < 4; ni++) {
                    cvt_frag(b[ni][0]);
                    cvt_frag(b[ni][1]);
                }
            }
#pragma unroll
            for (int mi = 0; mi < 4; mi++)
#pragma unroll
                for (int ni = 0; ni < 4; ni++)
                    mma_tf32(acc[mi][ni], a[mi], b[ni]);
        }
    }
#undef ISSUE

    // ---------------- epilogue ----------------
#pragma unroll
    for (int mi = 0; mi < 4; mi++) {
        const int row = m0 + wm * 64 + mi * 16 + q;
        float bm0 = 0.f, bm8 = 0.f;
        if (bias_mode == 2) { bm0 = __ldg(bias + row); bm8 = __ldg(bias + row + 8); }
#pragma unroll
        for (int ni = 0; ni < 4; ni++) {
            const int col = n0 + wn * 32 + ni * 8 + 2 * mq;
            float bn0 = 0.f, bn1 = 0.f;
            if (bias_mode == 1) { bn0 = __ldg(bias + col); bn1 = __ldg(bias + col + 1); }
            float v00 = acc[mi][ni][0] * alpha;
            float v01 = acc[mi][ni][1] * alpha;
            float v10 = acc[mi][ni][2] * alpha;
            float v11 = acc[mi][ni][3] * alpha;
            if (bias_mode == 1) { v00 += bn0; v01 += bn1; v10 += bn0; v11 += bn1; }
            else if (bias_mode == 2) { v00 += bm0; v01 += bm0; v10 += bm8; v11 += bm8; }
            if (round_out) {
                v00 = to_tf32(v00); v01 = to_tf32(v01);
                v10 = to_tf32(v10); v11 = to_tf32(v11);
            }
            *(float2*)(C + (size_t)row * ldc + col)       = make_float2(v00, v01);
            *(float2*)(C + (size_t)(row + 8) * ldc + col) = make_float2(v10, v11);
        }
    }
}

// ---------------- transpose (LN params only): in (R, C) -> out (C, R) ----------
__global__ __launch_bounds__(256)
void transpose_kernel(const float* __restrict__ in, float* __restrict__ out,
                      int R, int C)
{
    __shared__ float t[32][33];
    int c = blockIdx.x * 32 + threadIdx.x;
#pragma unroll
    for (int i = 0; i < 4; i++) {
        int r = blockIdx.y * 32 + threadIdx.y + i * 8;
        t[threadIdx.y + i * 8][threadIdx.x] = in[(size_t)r * C + c];
    }
    __syncthreads();
    int r2 = blockIdx.y * 32 + threadIdx.x;
#pragma unroll
    for (int i = 0; i < 4; i++) {
        int c2 = blockIdx.x * 32 + threadIdx.y + i * 8;
        out[(size_t)c2 * R + r2] = t[threadIdx.x][threadIdx.y + i * 8];
    }
}

// ---------------- elementwise tf32 round copy (weights) ----------------
__global__ __launch_bounds__(256)
void round_copy_kernel(const float* __restrict__ in, float* __restrict__ out)
{
    size_t i = (size_t)blockIdx.x * blockDim.x + threadIdx.x;
    float4 v = ((const float4*)in)[i];
    v.x = to_tf32(v.x); v.y = to_tf32(v.y); v.z = to_tf32(v.z); v.w = to_tf32(v.w);
    ((float4*)out)[i] = v;
}

// ---------------- softmax over L=2048, one block per row; tf32-rounded output ----------
__global__ __launch_bounds__(256)
void softmax_kernel(float* __restrict__ sc)
{
    float* p = sc + (size_t)blockIdx.x * L_;
    const int tid = threadIdx.x;
    float v[8];
    float mx = -1e30f;
#pragma unroll
    for (int i = 0; i < 8; i++) { v[i] = p[tid + i * 256]; mx = fmaxf(mx, v[i]); }
#pragma unroll
    for (int o = 16; o; o >>= 1) mx = fmaxf(mx, __shfl_xor_sync(0xffffffffu, mx, o));
    __shared__ float smax[8], ssum[8];
    if ((tid & 31) == 0) smax[tid >> 5] = mx;
    __syncthreads();
    float m2 = smax[0];
#pragma unroll
    for (int i = 1; i < 8; i++) m2 = fmaxf(m2, smax[i]);
    float s = 0.f;
#pragma unroll
    for (int i = 0; i < 8; i++) { v[i] = __expf(v[i] - m2); s += v[i]; }
#pragma unroll
    for (int o = 16; o; o >>= 1) s += __shfl_xor_sync(0xffffffffu, s, o);
    if ((tid & 31) == 0) ssum[tid >> 5] = s;
    __syncthreads();
    float tot = 0.f;
#pragma unroll
    for (int i = 0; i < 8; i++) tot += ssum[i];
    float inv = 1.f / tot;
#pragma unroll
    for (int i = 0; i < 8; i++) p[tid + i * 256] = to_tf32(v[i] * inv);
}

// ---------------- layernorm stats: one block per batch ----------------
__global__ __launch_bounds__(512)
void ln_stats_kernel(const float* __restrict__ x, float* __restrict__ stats)
{
    const float* xb = x + (size_t)blockIdx.x * (LAT_ * S_);
    float s = 0.f, ss = 0.f;
    for (int i = threadIdx.x; i < LAT_ * S_; i += 512) {
        float v = xb[i];
        s += v;
        ss = fmaf(v, v, ss);
    }
#pragma unroll
    for (int o = 16; o; o >>= 1) {
        s  += __shfl_xor_sync(0xffffffffu, s, o);
        ss += __shfl_xor_sync(0xffffffffu, ss, o);
    }
    __shared__ float rs[16], rss[16];
    if ((threadIdx.x & 31) == 0) { rs[threadIdx.x >> 5] = s; rss[threadIdx.x >> 5] = ss; }
    __syncthreads();
    if (threadIdx.x == 0) {
        float S = 0.f, SSq = 0.f;
#pragma unroll
        for (int i = 0; i < 16; i++) { S += rs[i]; SSq += rss[i]; }
        const float invN = 1.f / (float)(LAT_ * S_);
        float mu  = S * invN;
        float var = SSq * invN - mu * mu;
        stats[blockIdx.x * 2 + 0] = mu;
        stats[blockIdx.x * 2 + 1] = rsqrtf(var + 1e-5f);
    }
}

// ---------------- normalize + affine + relu, tf32-rounded output ----------------
__global__ __launch_bounds__(256)
void norm_relu_kernel(const float* __restrict__ attn, const float* __restrict__ lnw,
                      const float* __restrict__ lnb, const float* __restrict__ stats,
                      float* __restrict__ out)
{
    size_t i4 = (size_t)blockIdx.x * blockDim.x + threadIdx.x;
    int n  = (int)(i4 >> 16);       // LAT*S/4 = 65536 float4 per batch
    int cs = (int)(i4 & 65535);
    float mu = stats[n * 2 + 0];
    float r  = stats[n * 2 + 1];
    float4 x = ((const float4*)attn)[i4];
    float4 w = ((const float4*)lnw)[cs];
    float4 b = ((const float4*)lnb)[cs];
    float4 y;
    y.x = to_tf32(fmaxf(fmaf((x.x - mu) * r, w.x, b.x), 0.f));
    y.y = to_tf32(fmaxf(fmaf((x.y - mu) * r, w.y, b.y), 0.f));
    y.z = to_tf32(fmaxf(fmaf((x.z - mu) * r, w.z, b.z), 0.f));
    y.w = to_tf32(fmaxf(fmaf((x.w - mu) * r, w.w, b.w), 0.f));
    ((float4*)out)[i4] = y;
}

// ---------------- launch ----------------
extern "C" void kernel_launch(void* const* d_in, const int* in_sizes, int n_in,
                              void* d_out, int out_size)
{
    const float* st    = (const float*)d_in[0];
    const float* lt    = (const float*)d_in[1];
    const float* w_st  = (const float*)d_in[2];
    const float* b_st  = (const float*)d_in[3];
    const float* w_lt  = (const float*)d_in[4];
    const float* b_lt  = (const float*)d_in[5];
    const float* w_g   = (const float*)d_in[6];
    const float* b_g   = (const float*)d_in[7];
    const float* ln_w  = (const float*)d_in[8];
    const float* ln_b  = (const float*)d_in[9];
    const float* w_out = (const float*)d_in[10];
    const float* b_out = (const float*)d_in[11];
    float* out = (float*)d_out;

    float *thetaT, *phiT, *gb, *sc, *attnT, *nrmT, *lnTw, *lnTb, *stats;
    float *wstR, *wltR, *wgR, *woutR;
    cudaGetSymbolAddress((void**)&thetaT, g_thetaT);
    cudaGetSymbolAddress((void**)&phiT,   g_phiT);
    cudaGetSymbolAddress((void**)&gb,     g_g);
    cudaGetSymbolAddress((void**)&sc,     g_sc);
    cudaGetSymbolAddress((void**)&attnT,  g_attnT);
    cudaGetSymbolAddress((void**)&nrmT,   g_nrmT);
    cudaGetSymbolAddress((void**)&lnTw,   g_lnTw);
    cudaGetSymbolAddress((void**)&lnTb,   g_lnTb);
    cudaGetSymbolAddress((void**)&stats,  g_stats);
    cudaGetSymbolAddress((void**)&wstR,   g_wstR);
    cudaGetSymbolAddress((void**)&wltR,   g_wltR);
    cudaGetSymbolAddress((void**)&wgR,    g_wgR);
    cudaGetSymbolAddress((void**)&woutR,  g_woutR);

    cudaFuncSetAttribute(gemm_mma<0,0,0,0>, cudaFuncAttributeMaxDynamicSharedMemorySize, GEMM_SMEM);
    cudaFuncSetAttribute(gemm_mma<1,0,1,0>, cudaFuncAttributeMaxDynamicSharedMemorySize, GEMM_SMEM);
    cudaFuncSetAttribute(gemm_mma<0,1,0,1>, cudaFuncAttributeMaxDynamicSharedMemorySize, GEMM_SMEM);

    const float inv_sqrt_lat = 0.044194173824159216f;   // 1/sqrt(512)
    dim3 tb(32, 8);

    // tiny pre-pass: LN param transposes + weight tf32 rounding
    transpose_kernel<<<dim3(S_ / 32, LAT_ / 32), tb>>>(ln_w, lnTw, LAT_, S_);
    transpose_kernel<<<dim3(S_ / 32, LAT_ / 32), tb>>>(ln_b, lnTb, LAT_, S_);
    round_copy_kernel<<<(LAT_ * C_ST_ / 4) / 256, 256>>>(w_st, wstR);
    round_copy_kernel<<<(LAT_ * C_LT_ / 4) / 256, 256>>>(w_lt, wltR);
    round_copy_kernel<<<(LAT_ * C_LT_ / 4) / 256, 256>>>(w_g, wgR);
    round_copy_kernel<<<(C_ST_ * LAT_ / 4) / 256, 256>>>(w_out, woutR);

    // 1) thetaT[s][o] = sum_c st[c][s] * w_st[o][c] + b_st[o]    (A transposed, round A)
    gemm_mma<1,0,1,0><<<dim3(LAT_ / 128, S_ / 128, NBATCH), 256, GEMM_SMEM>>>(
        st, wstR, thetaT, b_st, C_ST_, S_, C_ST_, LAT_,
        (size_t)C_ST_ * S_, 0, (size_t)S_ * LAT_, 1.f, 1, 1);

    // 2) phiT[l][o] = sum_c lt[c][l] * w_lt[o][c] + b_lt[o]      (A transposed, round A)
    gemm_mma<1,0,1,0><<<dim3(LAT_ / 128, L_ / 128, NBATCH), 256, GEMM_SMEM>>>(
        lt, wltR, phiT, b_lt, C_LT_, L_, C_LT_, LAT_,
        (size_t)C_LT_ * L_, 0, (size_t)L_ * LAT_, 1.f, 1, 1);

    // 3) g[o][l] = sum_c w_g[o][c] * lt[c][l] + b_g[o]           (B transposed, round B)
    gemm_mma<0,1,0,1><<<dim3(L_ / 128, LAT_ / 128, NBATCH), 256, GEMM_SMEM>>>(
        wgR, lt, gb, b_g, C_LT_, C_LT_, L_, L_,
        0, (size_t)C_LT_ * L_, (size_t)LAT_ * L_, 1.f, 2, 1);

    // 4) scores[s][l] = (1/sqrt(LAT)) * sum_o thetaT[s][o] * phiT[l][o]
    gemm_mma<0,0,0,0><<<dim3(L_ / 128, S_ / 128, NBATCH), 256, GEMM_SMEM>>>(
        thetaT, phiT, sc, nullptr, LAT_, LAT_, LAT_, L_,
        (size_t)S_ * LAT_, (size_t)L_ * LAT_, (size_t)S_ * L_, inv_sqrt_lat, 0, 0);

    // 5) softmax over L (in place, rounded output)
    softmax_kernel<<<NBATCH * S_, 256>>>(sc);

    // 6) attnT[s][c] = sum_l p[s][l] * g[c][l]
    gemm_mma<0,0,0,0><<<dim3(LAT_ / 128, S_ / 128, NBATCH), 256, GEMM_SMEM>>>(
        sc, gb, attnT, nullptr, L_, L_, L_, LAT_,
        (size_t)S_ * L_, (size_t)LAT_ * L_, (size_t)S_ * LAT_, 1.f, 0, 0);

    // 7) layernorm stats + normalize + relu (rounded output)
    ln_stats_kernel<<<NBATCH, 512>>>(attnT, stats);
    norm_relu_kernel<<<(NBATCH * LAT_ * S_ / 4) / 256, 256>>>(attnT, lnTw, lnTb, stats, nrmT);

    // 8) out[o][s] = sum_c w_out[o][c] * nrmT[s][c] + b_out[o]
    gemm_mma<0,0,0,0><<<dim3(S_ / 128, C_ST_ / 128, NBATCH), 256, GEMM_SMEM>>>(
        woutR, nrmT, out, b_out, LAT_, LAT_, LAT_, S_,
        0, (size_t)S_ * LAT_, (size_t)C_ST_ * S_, 1.f, 2, 0);
}

// round 9
// speedup vs baseline: 4.0434x; 1.0562x over previous
#include <cuda_runtime.h>
#include <cstdint>
#include <math.h>

#define NBATCH 32
#define C_ST_  2048
#define C_LT_  2048
#define LAT_   512
#define S_     512
#define L_     2048

// ---------------- scratch (__device__ globals; no allocation) ----------------
__device__ float g_thetaT[(size_t)NBATCH * S_ * LAT_];    // (n, S, LAT)   tf32-rounded
__device__ float g_pg   [(size_t)NBATCH * 1024 * L_];     // (n, 1024, L): rows 0..511 phi[o][l], 512..1023 g[o][l]
__device__ float g_sc   [(size_t)NBATCH * S_ * L_];       // (n, S, L)
__device__ float g_attnT[(size_t)NBATCH * S_ * LAT_];     // (n, S, LAT)
__device__ float g_nrmT [(size_t)NBATCH * S_ * LAT_];     // (n, S, LAT)   tf32-rounded
__device__ float g_lnTw [(size_t)S_ * LAT_];
__device__ float g_lnTb [(size_t)S_ * LAT_];
__device__ float2 g_part[NBATCH * 16];
__device__ float g_stats[NBATCH * 2];
__device__ float g_wstR [(size_t)LAT_ * C_ST_];           // tf32-rounded weights
__device__ float g_wLG  [(size_t)1024 * C_LT_];           // stacked [w_lt; w_g], tf32-rounded
__device__ float g_bLG  [1024];                           // stacked [b_lt; b_g]
__device__ float g_woutR[(size_t)C_ST_ * LAT_];

// ---------------- helpers ----------------
__device__ __forceinline__ uint32_t smem_u32(const void* p) {
    uint32_t a;
    asm("{ .reg .u64 t; cvta.to.shared.u64 t, %1; cvt.u32.u64 %0, t; }" : "=r"(a) : "l"(p));
    return a;
}
__device__ __forceinline__ float to_tf32(float x) {
    float y;
    asm("cvt.rna.tf32.f32 %0, %1;" : "=f"(y) : "f"(x));
    return y;
}
__device__ __forceinline__ void cvt_frag(uint32_t& u) {
    float f = __uint_as_float(u);
    u = __float_as_uint(to_tf32(f));
}
#define CP_ASYNC16(dst, src) \
    asm volatile("cp.async.cg.shared.global [%0], [%1], 16;" :: "r"(dst), "l"(src))
#define CP_COMMIT() asm volatile("cp.async.commit_group;")
#define CP_WAIT1()  asm volatile("cp.async.wait_group 1;")

__device__ __forceinline__ uint32_t lds32(uint32_t addr) {
    uint32_t v;
    asm volatile("ld.shared.b32 %0, [%1];" : "=r"(v) : "r"(addr));
    return v;
}
__device__ __forceinline__ void mma_tf32(float* d, const uint32_t* a, const uint32_t* b) {
    asm volatile(
        "mma.sync.aligned.m16n8k8.row.col.f32.tf32.tf32.f32 "
        "{%0,%1,%2,%3},{%4,%5,%6,%7},{%8,%9},{%0,%1,%2,%3};"
        : "+f"(d[0]), "+f"(d[1]), "+f"(d[2]), "+f"(d[3])
        : "r"(a[0]), "r"(a[1]), "r"(a[2]), "r"(a[3]), "r"(b[0]), "r"(b[1]));
}

// ---------------- tf32 mma.sync GEMM: D[m][n] = alpha * sum_k A[m][k] B[n][k] (+bias) ----
// ATR=0: A stored [M][K] (m rows, k contig).  ATR=1: A stored [K][M] (k rows, m contig).
// Same for B/BTR with n. RA/RB: apply cvt.rna.tf32 to fragments (raw fp32 inputs).
// Tile 128x128x32, 256 threads, 3-stage cp.async, swizzled smem.
#define NST 3
#define STAGE_BYTES 32768                 // A 16KB + B 16KB
#define GEMM_SMEM (NST * STAGE_BYTES)     // 96 KB

template <int ATR, int BTR, int RA, int RB>
__global__ __launch_bounds__(256, 2)
void gemm_mma(const float* __restrict__ Ag, const float* __restrict__ Bg,
              float* __restrict__ Cg, const float* __restrict__ bias,
              int K, int lda, int ldb, int ldc,
              size_t sA, size_t sB, size_t sC, float alpha,
              int bias_mode, int round_out)
{
    extern __shared__ char smem[];
    const uint32_t sbase = smem_u32(smem);
    const int tid  = threadIdx.x;
    const int wid  = tid >> 5;
    const int lane = tid & 31;
    const int q    = lane >> 2;       // 0..7
    const int mq   = lane & 3;        // 0..3
    const int wm   = wid >> 2;        // 0..1 (m: 2 x 64)
    const int wn   = wid & 3;         // 0..3 (n: 4 x 32)
    const int m0   = blockIdx.y * 128;
    const int n0   = blockIdx.x * 128;

    const float* A = Ag + (size_t)blockIdx.z * sA + (ATR ? (size_t)m0 : (size_t)m0 * lda);
    const float* B = Bg + (size_t)blockIdx.z * sB + (BTR ? (size_t)n0 : (size_t)n0 * ldb);
    float*       C = Cg + (size_t)blockIdx.z * sC;

    // staging offsets: 4 chunks each for A and B per thread
    size_t   gAoff[4], gBoff[4];
    uint32_t sAoff[4], sBoff[4];
#pragma unroll
    for (int j = 0; j < 4; j++) {
        int id = tid + 256 * j;       // 0..1023
        if (ATR) {
            int kr = id >> 5, c4 = id & 31;
            gAoff[j] = (size_t)kr * lda + c4 * 4;
            sAoff[j] = kr * 512 + ((c4 * 16) ^ ((kr & 3) << 5));
        } else {
            int r = id >> 3, c4 = id & 7;
            gAoff[j] = (size_t)r * lda + c4 * 4;
            sAoff[j] = r * 128 + ((c4 ^ (r & 7)) << 4);
        }
        if (BTR) {
            int kr = id >> 5, c4 = id & 31;
            gBoff[j] = (size_t)kr * ldb + c4 * 4;
            sBoff[j] = 16384 + kr * 512 + ((c4 * 16) ^ ((kr & 3) << 5));
        } else {
            int r = id >> 3, c4 = id & 7;
            gBoff[j] = (size_t)r * ldb + c4 * 4;
            sBoff[j] = 16384 + r * 128 + ((c4 ^ (r & 7)) << 4);
        }
    }
    const size_t aAdv = ATR ? (size_t)32 * lda : (size_t)32;
    const size_t bAdv = BTR ? (size_t)32 * ldb : (size_t)32;

    const int KT = K >> 5;

#define ISSUE(it_) do {                                                  \
        int s_ = (it_) % NST;                                            \
        uint32_t base_ = sbase + s_ * STAGE_BYTES;                       \
        const float* Ai_ = A + (size_t)(it_) * aAdv;                     \
        const float* Bi_ = B + (size_t)(it_) * bAdv;                     \
        _Pragma("unroll")                                                \
        for (int j = 0; j < 4; j++) {                                    \
            CP_ASYNC16(base_ + sAoff[j], Ai_ + gAoff[j]);                \
            CP_ASYNC16(base_ + sBoff[j], Bi_ + gBoff[j]);                \
        }                                                                \
    } while (0)

    ISSUE(0); CP_COMMIT();
    ISSUE(1); CP_COMMIT();

    float acc[4][4][4];
#pragma unroll
    for (int mi = 0; mi < 4; mi++)
#pragma unroll
        for (int ni = 0; ni < 4; ni++)
#pragma unroll
            for (int r = 0; r < 4; r++) acc[mi][ni][r] = 0.f;

    // fragment address bases
    uint32_t aBase[4], bBase[4];        // non-transposed mode
    uint32_t amLo[4], amHi[4];          // AT mode (byte offsets, swizzled)
    uint32_t bnLo[4];                   // BT mode
    const uint32_t swz = (uint32_t)(mq << 5);
#pragma unroll
    for (int mi = 0; mi < 4; mi++) {
        int m = wm * 64 + mi * 16 + q;
        aBase[mi] = m * 128 + mq * 4;
        amLo[mi]  = ((uint32_t)(m * 4)) ^ swz;
        amHi[mi]  = ((uint32_t)((m + 8) * 4)) ^ swz;
    }
#pragma unroll
    for (int ni = 0; ni < 4; ni++) {
        int n = wn * 32 + ni * 8 + q;
        bBase[ni] = n * 128 + mq * 4 + 16384;
        bnLo[ni]  = ((uint32_t)(n * 4)) ^ swz;
    }

    for (int it = 0; it < KT; ++it) {
        CP_WAIT1();
        __syncthreads();
        if (it + 2 < KT) ISSUE(it + 2);
        CP_COMMIT();

        const uint32_t buf = sbase + (it % NST) * STAGE_BYTES;
#pragma unroll
        for (int ki = 0; ki < 4; ki++) {
            uint32_t a[4][4], b[4][2];
            if (ATR) {
                const uint32_t kA = buf + ki * 4096 + mq * 512;
#pragma unroll
                for (int mi = 0; mi < 4; mi++) {
                    a[mi][0] = lds32(kA + amLo[mi]);
                    a[mi][1] = lds32(kA + amHi[mi]);
                    a[mi][2] = lds32(kA + 2048 + amLo[mi]);
                    a[mi][3] = lds32(kA + 2048 + amHi[mi]);
                }
            } else {
                const uint32_t c0 = (uint32_t)(((2 * ki) ^ q) << 4);
                const uint32_t c1 = (uint32_t)(((2 * ki + 1) ^ q) << 4);
#pragma unroll
                for (int mi = 0; mi < 4; mi++) {
                    uint32_t ad = buf + aBase[mi];
                    a[mi][0] = lds32(ad + c0);
                    a[mi][1] = lds32(ad + 1024 + c0);
                    a[mi][2] = lds32(ad + c1);
                    a[mi][3] = lds32(ad + 1024 + c1);
                }
            }
            if (BTR) {
                const uint32_t kB = buf + 16384 + ki * 4096 + mq * 512;
#pragma unroll
                for (int ni = 0; ni < 4; ni++) {
                    b[ni][0] = lds32(kB + bnLo[ni]);
                    b[ni][1] = lds32(kB + 2048 + bnLo[ni]);
                }
            } else {
                const uint32_t c0 = (uint32_t)(((2 * ki) ^ q) << 4);
                const uint32_t c1 = (uint32_t)(((2 * ki + 1) ^ q) << 4);
#pragma unroll
                for (int ni = 0; ni < 4; ni++) {
                    uint32_t bd = buf + bBase[ni];
                    b[ni][0] = lds32(bd + c0);
                    b[ni][1] = lds32(bd + c1);
                }
            }
            if (RA) {
#pragma unroll
                for (int mi = 0; mi < 4; mi++)
#pragma unroll
                    for (int r = 0; r < 4; r++) cvt_frag(a[mi][r]);
            }
            if (RB) {
#pragma unroll
                for (int ni = 0; ni < 4; ni++) {
                    cvt_frag(b[ni][0]);
                    cvt_frag(b[ni][1]);
                }
            }
#pragma unroll
            for (int mi = 0; mi < 4; mi++)
#pragma unroll
                for (int ni = 0; ni < 4; ni++)
                    mma_tf32(acc[mi][ni], a[mi], b[ni]);
        }
    }
#undef ISSUE

    // ---------------- epilogue ----------------
#pragma unroll
    for (int mi = 0; mi < 4; mi++) {
        const int row = m0 + wm * 64 + mi * 16 + q;
        float bm0 = 0.f, bm8 = 0.f;
        if (bias_mode == 2) { bm0 = __ldg(bias + row); bm8 = __ldg(bias + row + 8); }
#pragma unroll
        for (int ni = 0; ni < 4; ni++) {
            const int col = n0 + wn * 32 + ni * 8 + 2 * mq;
            float bn0 = 0.f, bn1 = 0.f;
            if (bias_mode == 1) { bn0 = __ldg(bias + col); bn1 = __ldg(bias + col + 1); }
            float v00 = acc[mi][ni][0] * alpha;
            float v01 = acc[mi][ni][1] * alpha;
            float v10 = acc[mi][ni][2] * alpha;
            float v11 = acc[mi][ni][3] * alpha;
            if (bias_mode == 1) { v00 += bn0; v01 += bn1; v10 += bn0; v11 += bn1; }
            else if (bias_mode == 2) { v00 += bm0; v01 += bm0; v10 += bm8; v11 += bm8; }
            if (round_out) {
                v00 = to_tf32(v00); v01 = to_tf32(v01);
                v10 = to_tf32(v10); v11 = to_tf32(v11);
            }
            *(float2*)(C + (size_t)row * ldc + col)       = make_float2(v00, v01);
            *(float2*)(C + (size_t)(row + 8) * ldc + col) = make_float2(v10, v11);
        }
    }
}

// ---------------- transpose (LN params only): in (R, C) -> out (C, R) ----------
__global__ __launch_bounds__(256)
void transpose_kernel(const float* __restrict__ in, float* __restrict__ out,
                      int R, int C)
{
    __shared__ float t[32][33];
    int c = blockIdx.x * 32 + threadIdx.x;
#pragma unroll
    for (int i = 0; i < 4; i++) {
        int r = blockIdx.y * 32 + threadIdx.y + i * 8;
        t[threadIdx.y + i * 8][threadIdx.x] = in[(size_t)r * C + c];
    }
    __syncthreads();
    int r2 = blockIdx.y * 32 + threadIdx.x;
#pragma unroll
    for (int i = 0; i < 4; i++) {
        int c2 = blockIdx.x * 32 + threadIdx.y + i * 8;
        out[(size_t)c2 * R + r2] = t[threadIdx.x][threadIdx.y + i * 8];
    }
}

// ---------------- elementwise tf32 round copy (weights) ----------------
__global__ __launch_bounds__(256)
void round_copy_kernel(const float* __restrict__ in, float* __restrict__ out)
{
    size_t i = (size_t)blockIdx.x * blockDim.x + threadIdx.x;
    float4 v = ((const float4*)in)[i];
    v.x = to_tf32(v.x); v.y = to_tf32(v.y); v.z = to_tf32(v.z); v.w = to_tf32(v.w);
    ((float4*)out)[i] = v;
}

// ---------------- stack biases: out[0:512)=b_lt, out[512:1024)=b_g ----------------
__global__ void stack_bias_kernel(const float* __restrict__ b0, const float* __restrict__ b1,
                                  float* __restrict__ out)
{
    int i = threadIdx.x + blockIdx.x * blockDim.x;
    out[i] = (i < 512) ? b0[i] : b1[i - 512];
}

// ---------------- softmax over L=2048, one block per row; tf32-rounded output ----------
__global__ __launch_bounds__(256)
void softmax_kernel(float* __restrict__ sc)
{
    float* p = sc + (size_t)blockIdx.x * L_;
    const int tid = threadIdx.x;
    float v[8];
    float mx = -1e30f;
#pragma unroll
    for (int i = 0; i < 8; i++) { v[i] = p[tid + i * 256]; mx = fmaxf(mx, v[i]); }
#pragma unroll
    for (int o = 16; o; o >>= 1) mx = fmaxf(mx, __shfl_xor_sync(0xffffffffu, mx, o));
    __shared__ float smax[8], ssum[8];
    if ((tid & 31) == 0) smax[tid >> 5] = mx;
    __syncthreads();
    float m2 = smax[0];
#pragma unroll
    for (int i = 1; i < 8; i++) m2 = fmaxf(m2, smax[i]);
    float s = 0.f;
#pragma unroll
    for (int i = 0; i < 8; i++) { v[i] = __expf(v[i] - m2); s += v[i]; }
#pragma unroll
    for (int o = 16; o; o >>= 1) s += __shfl_xor_sync(0xffffffffu, s, o);
    if ((tid & 31) == 0) ssum[tid >> 5] = s;
    __syncthreads();
    float tot = 0.f;
#pragma unroll
    for (int i = 0; i < 8; i++) tot += ssum[i];
    float inv = 1.f / tot;
#pragma unroll
    for (int i = 0; i < 8; i++) p[tid + i * 256] = to_tf32(v[i] * inv);
}

// ---------------- layernorm stats phase 1: 16 partials per batch ----------------
__global__ __launch_bounds__(256)
void ln_part_kernel(const float* __restrict__ x, float2* __restrict__ part)
{
    const int batch = blockIdx.y;
    const int p     = blockIdx.x;           // 0..15
    const float4* xb = (const float4*)(x + (size_t)batch * (LAT_ * S_) + p * 16384);
    float s = 0.f, ss = 0.f;
#pragma unroll
    for (int i = 0; i < 16; i++) {
        float4 v = xb[threadIdx.x + i * 256];
        s  += v.x + v.y + v.z + v.w;
        ss += v.x * v.x + v.y * v.y + v.z * v.z + v.w * v.w;
    }
#pragma unroll
    for (int o = 16; o; o >>= 1) {
        s  += __shfl_xor_sync(0xffffffffu, s, o);
        ss += __shfl_xor_sync(0xffffffffu, ss, o);
    }
    __shared__ float rs[8], rss[8];
    if ((threadIdx.x & 31) == 0) { rs[threadIdx.x >> 5] = s; rss[threadIdx.x >> 5] = ss; }
    __syncthreads();
    if (threadIdx.x == 0) {
        float S = 0.f, SSq = 0.f;
#pragma unroll
        for (int i = 0; i < 8; i++) { S += rs[i]; SSq += rss[i]; }
        part[batch * 16 + p] = make_float2(S, SSq);
    }
}

// ---------------- layernorm stats phase 2: finalize ----------------
__global__ void ln_final_kernel(const float2* __restrict__ part, float* __restrict__ stats)
{
    int b = threadIdx.x;   // 0..31
    float S = 0.f, SSq = 0.f;
#pragma unroll
    for (int i = 0; i < 16; i++) {
        float2 v = part[b * 16 + i];
        S += v.x; SSq += v.y;
    }
    const float invN = 1.f / (float)(LAT_ * S_);
    float mu  = S * invN;
    float var = SSq * invN - mu * mu;
    stats[b * 2 + 0] = mu;
    stats[b * 2 + 1] = rsqrtf(var + 1e-5f);
}

// ---------------- normalize + affine + relu, tf32-rounded output ----------------
__global__ __launch_bounds__(256)
void norm_relu_kernel(const float* __restrict__ attn, const float* __restrict__ lnw,
                      const float* __restrict__ lnb, const float* __restrict__ stats,
                      float* __restrict__ out)
{
    size_t i4 = (size_t)blockIdx.x * blockDim.x + threadIdx.x;
    int n  = (int)(i4 >> 16);       // LAT*S/4 = 65536 float4 per batch
    int cs = (int)(i4 & 65535);
    float mu = stats[n * 2 + 0];
    float r  = stats[n * 2 + 1];
    float4 x = ((const float4*)attn)[i4];
    float4 w = ((const float4*)lnw)[cs];
    float4 b = ((const float4*)lnb)[cs];
    float4 y;
    y.x = to_tf32(fmaxf(fmaf((x.x - mu) * r, w.x, b.x), 0.f));
    y.y = to_tf32(fmaxf(fmaf((x.y - mu) * r, w.y, b.y), 0.f));
    y.z = to_tf32(fmaxf(fmaf((x.z - mu) * r, w.z, b.z), 0.f));
    y.w = to_tf32(fmaxf(fmaf((x.w - mu) * r, w.w, b.w), 0.f));
    ((float4*)out)[i4] = y;
}

// ---------------- launch ----------------
extern "C" void kernel_launch(void* const* d_in, const int* in_sizes, int n_in,
                              void* d_out, int out_size)
{
    const float* st    = (const float*)d_in[0];
    const float* lt    = (const float*)d_in[1];
    const float* w_st  = (const float*)d_in[2];
    const float* b_st  = (const float*)d_in[3];
    const float* w_lt  = (const float*)d_in[4];
    const float* b_lt  = (const float*)d_in[5];
    const float* w_g   = (const float*)d_in[6];
    const float* b_g   = (const float*)d_in[7];
    const float* ln_w  = (const float*)d_in[8];
    const float* ln_b  = (const float*)d_in[9];
    const float* w_out = (const float*)d_in[10];
    const float* b_out = (const float*)d_in[11];
    float* out = (float*)d_out;

    float *thetaT, *pg, *sc, *attnT, *nrmT, *lnTw, *lnTb, *stats;
    float *wstR, *wLG, *bLG, *woutR;
    float2 *part;
    cudaGetSymbolAddress((void**)&thetaT, g_thetaT);
    cudaGetSymbolAddress((void**)&pg,     g_pg);
    cudaGetSymbolAddress((void**)&sc,     g_sc);
    cudaGetSymbolAddress((void**)&attnT,  g_attnT);
    cudaGetSymbolAddress((void**)&nrmT,   g_nrmT);
    cudaGetSymbolAddress((void**)&lnTw,   g_lnTw);
    cudaGetSymbolAddress((void**)&lnTb,   g_lnTb);
    cudaGetSymbolAddress((void**)&part,   g_part);
    cudaGetSymbolAddress((void**)&stats,  g_stats);
    cudaGetSymbolAddress((void**)&wstR,   g_wstR);
    cudaGetSymbolAddress((void**)&wLG,    g_wLG);
    cudaGetSymbolAddress((void**)&bLG,    g_bLG);
    cudaGetSymbolAddress((void**)&woutR,  g_woutR);

    cudaFuncSetAttribute(gemm_mma<0,0,0,0>, cudaFuncAttributeMaxDynamicSharedMemorySize, GEMM_SMEM);
    cudaFuncSetAttribute(gemm_mma<1,0,1,0>, cudaFuncAttributeMaxDynamicSharedMemorySize, GEMM_SMEM);
    cudaFuncSetAttribute(gemm_mma<0,1,0,1>, cudaFuncAttributeMaxDynamicSharedMemorySize, GEMM_SMEM);
    cudaFuncSetAttribute(gemm_mma<0,1,0,0>, cudaFuncAttributeMaxDynamicSharedMemorySize, GEMM_SMEM);

    const float inv_sqrt_lat = 0.044194173824159216f;   // 1/sqrt(512)
    dim3 tb(32, 8);

    // tiny pre-pass: LN param transposes + weight tf32 rounding + bias stacking
    transpose_kernel<<<dim3(S_ / 32, LAT_ / 32), tb>>>(ln_w, lnTw, LAT_, S_);
    transpose_kernel<<<dim3(S_ / 32, LAT_ / 32), tb>>>(ln_b, lnTb, LAT_, S_);
    round_copy_kernel<<<(LAT_ * C_ST_ / 4) / 256, 256>>>(w_st, wstR);
    round_copy_kernel<<<(LAT_ * C_LT_ / 4) / 256, 256>>>(w_lt, wLG);
    round_copy_kernel<<<(LAT_ * C_LT_ / 4) / 256, 256>>>(w_g, wLG + (size_t)512 * C_LT_);
    round_copy_kernel<<<(C_ST_ * LAT_ / 4) / 256, 256>>>(w_out, woutR);
    stack_bias_kernel<<<4, 256>>>(b_lt, b_g, bLG);

    // 1) thetaT[s][o] = sum_c st[c][s] * w_st[o][c] + b_st[o]    (A transposed, round A)
    gemm_mma<1,0,1,0><<<dim3(LAT_ / 128, S_ / 128, NBATCH), 256, GEMM_SMEM>>>(
        st, wstR, thetaT, b_st, C_ST_, S_, C_ST_, LAT_,
        (size_t)C_ST_ * S_, 0, (size_t)S_ * LAT_, 1.f, 1, 1);

    // 2) merged phi+g: pg[o2][l] = sum_c wLG[o2][c] * lt[c][l] + bLG[o2]
    //    rows 0..511 = phi[o][l], rows 512..1023 = g[o][l]   (B transposed, round B)
    gemm_mma<0,1,0,1><<<dim3(L_ / 128, 1024 / 128, NBATCH), 256, GEMM_SMEM>>>(
        wLG, lt, pg, bLG, C_LT_, C_LT_, L_, L_,
        0, (size_t)C_LT_ * L_, (size_t)1024 * L_, 1.f, 2, 1);

    // 3) scores[s][l] = (1/sqrt(LAT)) * sum_o thetaT[s][o] * phi[o][l]   (B transposed)
    gemm_mma<0,1,0,0><<<dim3(L_ / 128, S_ / 128, NBATCH), 256, GEMM_SMEM>>>(
        thetaT, pg, sc, nullptr, LAT_, LAT_, L_, L_,
        (size_t)S_ * LAT_, (size_t)1024 * L_, (size_t)S_ * L_, inv_sqrt_lat, 0, 0);

    // 4) softmax over L (in place, rounded output)
    softmax_kernel<<<NBATCH * S_, 256>>>(sc);

    // 5) attnT[s][c] = sum_l p[s][l] * g[c][l]
    gemm_mma<0,0,0,0><<<dim3(LAT_ / 128, S_ / 128, NBATCH), 256, GEMM_SMEM>>>(
        sc, pg + (size_t)512 * L_, attnT, nullptr, L_, L_, L_, LAT_,
        (size_t)S_ * L_, (size_t)1024 * L_, (size_t)S_ * LAT_, 1.f, 0, 0);

    // 6) layernorm stats (two-phase, full-chip) + normalize + relu (rounded output)
    ln_part_kernel<<<dim3(16, NBATCH), 256>>>(attnT, part);
    ln_final_kernel<<<1, 32>>>(part, stats);
    norm_relu_kernel<<<(NBATCH * LAT_ * S_ / 4) / 256, 256>>>(attnT, lnTw, lnTb, stats, nrmT);

    // 7) out[o][s] = sum_c w_out[o][c] * nrmT[s][c] + b_out[o]
    gemm_mma<0,0,0,0><<<dim3(S_ / 128, C_ST_ / 128, NBATCH), 256, GEMM_SMEM>>>(
        woutR, nrmT, out, b_out, LAT_, LAT_, LAT_, S_,
        0, (size_t)S_ * LAT_, (size_t)C_ST_ * S_, 1.f, 2, 0);
}

// round 10
// speedup vs baseline: 4.1500x; 1.0264x over previous
#include <cuda_runtime.h>
#include <cstdint>
#include <math.h>

#define NBATCH 32
#define C_ST_  2048
#define C_LT_  2048
#define LAT_   512
#define S_     512
#define L_     2048

// ---------------- scratch (__device__ globals; no allocation) ----------------
__device__ float g_thetaT[(size_t)NBATCH * S_ * LAT_];    // (n, S, LAT)   tf32-rounded
__device__ float g_pg   [(size_t)NBATCH * 1024 * L_];     // (n, 1024, L): rows 0..511 phi, 512..1023 g
__device__ float g_sc   [(size_t)NBATCH * S_ * L_];       // (n, S, L)
__device__ float g_attnT[(size_t)NBATCH * S_ * LAT_];     // (n, S, LAT)
__device__ float g_nrmT [(size_t)NBATCH * S_ * LAT_];     // (n, S, LAT)   tf32-rounded
__device__ float g_lnTw [(size_t)S_ * LAT_];
__device__ float g_lnTb [(size_t)S_ * LAT_];
__device__ float2 g_part[NBATCH * 16];
__device__ float g_stats[NBATCH * 2];
__device__ float g_wstR [(size_t)LAT_ * C_ST_];           // tf32-rounded weights
__device__ float g_wLG  [(size_t)1024 * C_LT_];           // stacked [w_lt; w_g], tf32-rounded
__device__ float g_bLG  [1024];                           // stacked [b_lt; b_g]
__device__ float g_woutR[(size_t)C_ST_ * LAT_];

// ---------------- helpers ----------------
__device__ __forceinline__ uint32_t smem_u32(const void* p) {
    uint32_t a;
    asm("{ .reg .u64 t; cvta.to.shared.u64 t, %1; cvt.u32.u64 %0, t; }" : "=r"(a) : "l"(p));
    return a;
}
__device__ __forceinline__ float to_tf32(float x) {
    float y;
    asm("cvt.rna.tf32.f32 %0, %1;" : "=f"(y) : "f"(x));
    return y;
}
__device__ __forceinline__ void cvt_frag(uint32_t& u) {
    float f = __uint_as_float(u);
    u = __float_as_uint(to_tf32(f));
}
#define CP_ASYNC16(dst, src) \
    asm volatile("cp.async.cg.shared.global [%0], [%1], 16;" :: "r"(dst), "l"(src))
#define CP_COMMIT() asm volatile("cp.async.commit_group;")
#define CP_WAIT1()  asm volatile("cp.async.wait_group 1;")

__device__ __forceinline__ uint32_t lds32(uint32_t addr) {
    uint32_t v;
    asm volatile("ld.shared.b32 %0, [%1];" : "=r"(v) : "r"(addr));
    return v;
}
__device__ __forceinline__ void mma_tf32(float* d, const uint32_t* a, const uint32_t* b) {
    asm volatile(
        "mma.sync.aligned.m16n8k8.row.col.f32.tf32.tf32.f32 "
        "{%0,%1,%2,%3},{%4,%5,%6,%7},{%8,%9},{%0,%1,%2,%3};"
        : "+f"(d[0]), "+f"(d[1]), "+f"(d[2]), "+f"(d[3])
        : "r"(a[0]), "r"(a[1]), "r"(a[2]), "r"(a[3]), "r"(b[0]), "r"(b[1]));
}

// ================= generic 128x128x32 GEMM (unchanged, HW-validated) =================
#define NST 3
#define STAGE_BYTES 32768
#define GEMM_SMEM (NST * STAGE_BYTES)     // 96 KB

template <int ATR, int BTR, int RA, int RB>
__global__ __launch_bounds__(256, 2)
void gemm_mma(const float* __restrict__ Ag, const float* __restrict__ Bg,
              float* __restrict__ Cg, const float* __restrict__ bias,
              int K, int lda, int ldb, int ldc,
              size_t sA, size_t sB, size_t sC, float alpha,
              int bias_mode, int round_out)
{
    extern __shared__ char smem[];
    const uint32_t sbase = smem_u32(smem);
    const int tid  = threadIdx.x;
    const int wid  = tid >> 5;
    const int lane = tid & 31;
    const int q    = lane >> 2;
    const int mq   = lane & 3;
    const int wm   = wid >> 2;
    const int wn   = wid & 3;
    const int m0   = blockIdx.y * 128;
    const int n0   = blockIdx.x * 128;

    const float* A = Ag + (size_t)blockIdx.z * sA + (ATR ? (size_t)m0 : (size_t)m0 * lda);
    const float* B = Bg + (size_t)blockIdx.z * sB + (BTR ? (size_t)n0 : (size_t)n0 * ldb);
    float*       C = Cg + (size_t)blockIdx.z * sC;

    size_t   gAoff[4], gBoff[4];
    uint32_t sAoff[4], sBoff[4];
#pragma unroll
    for (int j = 0; j < 4; j++) {
        int id = tid + 256 * j;
        if (ATR) {
            int kr = id >> 5, c4 = id & 31;
            gAoff[j] = (size_t)kr * lda + c4 * 4;
            sAoff[j] = kr * 512 + ((c4 * 16) ^ ((kr & 3) << 5));
        } else {
            int r = id >> 3, c4 = id & 7;
            gAoff[j] = (size_t)r * lda + c4 * 4;
            sAoff[j] = r * 128 + ((c4 ^ (r & 7)) << 4);
        }
        if (BTR) {
            int kr = id >> 5, c4 = id & 31;
            gBoff[j] = (size_t)kr * ldb + c4 * 4;
            sBoff[j] = 16384 + kr * 512 + ((c4 * 16) ^ ((kr & 3) << 5));
        } else {
            int r = id >> 3, c4 = id & 7;
            gBoff[j] = (size_t)r * ldb + c4 * 4;
            sBoff[j] = 16384 + r * 128 + ((c4 ^ (r & 7)) << 4);
        }
    }
    const size_t aAdv = ATR ? (size_t)32 * lda : (size_t)32;
    const size_t bAdv = BTR ? (size_t)32 * ldb : (size_t)32;
    const int KT = K >> 5;

#define ISSUE(it_) do {                                                  \
        int s_ = (it_) % NST;                                            \
        uint32_t base_ = sbase + s_ * STAGE_BYTES;                       \
        const float* Ai_ = A + (size_t)(it_) * aAdv;                     \
        const float* Bi_ = B + (size_t)(it_) * bAdv;                     \
        _Pragma("unroll")                                                \
        for (int j = 0; j < 4; j++) {                                    \
            CP_ASYNC16(base_ + sAoff[j], Ai_ + gAoff[j]);                \
            CP_ASYNC16(base_ + sBoff[j], Bi_ + gBoff[j]);                \
        }                                                                \
    } while (0)

    ISSUE(0); CP_COMMIT();
    ISSUE(1); CP_COMMIT();

    float acc[4][4][4];
#pragma unroll
    for (int mi = 0; mi < 4; mi++)
#pragma unroll
        for (int ni = 0; ni < 4; ni++)
#pragma unroll
            for (int r = 0; r < 4; r++) acc[mi][ni][r] = 0.f;

    uint32_t aBase[4], bBase[4];
    uint32_t amLo[4], amHi[4];
    uint32_t bnLo[4];
    const uint32_t swz = (uint32_t)(mq << 5);
#pragma unroll
    for (int mi = 0; mi < 4; mi++) {
        int m = wm * 64 + mi * 16 + q;
        aBase[mi] = m * 128 + mq * 4;
        amLo[mi]  = ((uint32_t)(m * 4)) ^ swz;
        amHi[mi]  = ((uint32_t)((m + 8) * 4)) ^ swz;
    }
#pragma unroll
    for (int ni = 0; ni < 4; ni++) {
        int n = wn * 32 + ni * 8 + q;
        bBase[ni] = n * 128 + mq * 4 + 16384;
        bnLo[ni]  = ((uint32_t)(n * 4)) ^ swz;
    }

    for (int it = 0; it < KT; ++it) {
        CP_WAIT1();
        __syncthreads();
        if (it + 2 < KT) ISSUE(it + 2);
        CP_COMMIT();

        const uint32_t buf = sbase + (it % NST) * STAGE_BYTES;
#pragma unroll
        for (int ki = 0; ki < 4; ki++) {
            uint32_t a[4][4], b[4][2];
            if (ATR) {
                const uint32_t kA = buf + ki * 4096 + mq * 512;
#pragma unroll
                for (int mi = 0; mi < 4; mi++) {
                    a[mi][0] = lds32(kA + amLo[mi]);
                    a[mi][1] = lds32(kA + amHi[mi]);
                    a[mi][2] = lds32(kA + 2048 + amLo[mi]);
                    a[mi][3] = lds32(kA + 2048 + amHi[mi]);
                }
            } else {
                const uint32_t c0 = (uint32_t)(((2 * ki) ^ q) << 4);
                const uint32_t c1 = (uint32_t)(((2 * ki + 1) ^ q) << 4);
#pragma unroll
                for (int mi = 0; mi < 4; mi++) {
                    uint32_t ad = buf + aBase[mi];
                    a[mi][0] = lds32(ad + c0);
                    a[mi][1] = lds32(ad + 1024 + c0);
                    a[mi][2] = lds32(ad + c1);
                    a[mi][3] = lds32(ad + 1024 + c1);
                }
            }
            if (BTR) {
                const uint32_t kB = buf + 16384 + ki * 4096 + mq * 512;
#pragma unroll
                for (int ni = 0; ni < 4; ni++) {
                    b[ni][0] = lds32(kB + bnLo[ni]);
                    b[ni][1] = lds32(kB + 2048 + bnLo[ni]);
                }
            } else {
                const uint32_t c0 = (uint32_t)(((2 * ki) ^ q) << 4);
                const uint32_t c1 = (uint32_t)(((2 * ki + 1) ^ q) << 4);
#pragma unroll
                for (int ni = 0; ni < 4; ni++) {
                    uint32_t bd = buf + bBase[ni];
                    b[ni][0] = lds32(bd + c0);
                    b[ni][1] = lds32(bd + c1);
                }
            }
            if (RA) {
#pragma unroll
                for (int mi = 0; mi < 4; mi++)
#pragma unroll
                    for (int r = 0; r < 4; r++) cvt_frag(a[mi][r]);
            }
            if (RB) {
#pragma unroll
                for (int ni = 0; ni < 4; ni++) { cvt_frag(b[ni][0]); cvt_frag(b[ni][1]); }
            }
#pragma unroll
            for (int mi = 0; mi < 4; mi++)
#pragma unroll
                for (int ni = 0; ni < 4; ni++)
                    mma_tf32(acc[mi][ni], a[mi], b[ni]);
        }
    }
#undef ISSUE

#pragma unroll
    for (int mi = 0; mi < 4; mi++) {
        const int row = m0 + wm * 64 + mi * 16 + q;
        float bm0 = 0.f, bm8 = 0.f;
        if (bias_mode == 2) { bm0 = __ldg(bias + row); bm8 = __ldg(bias + row + 8); }
#pragma unroll
        for (int ni = 0; ni < 4; ni++) {
            const int col = n0 + wn * 32 + ni * 8 + 2 * mq;
            float bn0 = 0.f, bn1 = 0.f;
            if (bias_mode == 1) { bn0 = __ldg(bias + col); bn1 = __ldg(bias + col + 1); }
            float v00 = acc[mi][ni][0] * alpha;
            float v01 = acc[mi][ni][1] * alpha;
            float v10 = acc[mi][ni][2] * alpha;
            float v11 = acc[mi][ni][3] * alpha;
            if (bias_mode == 1) { v00 += bn0; v01 += bn1; v10 += bn0; v11 += bn1; }
            else if (bias_mode == 2) { v00 += bm0; v01 += bm0; v10 += bm8; v11 += bm8; }
            if (round_out) {
                v00 = to_tf32(v00); v01 = to_tf32(v01);
                v10 = to_tf32(v10); v11 = to_tf32(v11);
            }
            *(float2*)(C + (size_t)row * ldc + col)       = make_float2(v00, v01);
            *(float2*)(C + (size_t)(row + 8) * ldc + col) = make_float2(v10, v11);
        }
    }
}

// ================= big-tile GEMM for merged phi+g: 128m x 256n x 32k ==============
// A: [M][K] k-contig (weights, pre-rounded). B: [K][N] (lt, raw -> cvt in regs).
// 8 warps = 2m x 4n, warp tile 64x64 (mi=4, ni=8). bias per-row, rounded output.
#define BNST 3
#define BSTG (16384 + 32768)            // A 16KB + B 32KB = 48KB/stage
#define GEMM_BIG_SMEM (BNST * BSTG)     // 144 KB

__global__ __launch_bounds__(256, 1)
void gemm_big(const float* __restrict__ Ag, const float* __restrict__ Bg,
              float* __restrict__ Cg, const float* __restrict__ bias,
              int K, int lda, int ldb, int ldc,
              size_t sB, size_t sC)
{
    extern __shared__ char smem[];
    const uint32_t sbase = smem_u32(smem);
    const int tid  = threadIdx.x;
    const int wid  = tid >> 5;
    const int lane = tid & 31;
    const int q    = lane >> 2;
    const int mq   = lane & 3;
    const int wm   = wid >> 2;        // 0..1
    const int wn   = wid & 3;         // 0..3
    const int m0   = blockIdx.y * 128;
    const int n0   = blockIdx.x * 256;

    const float* A = Ag + (size_t)m0 * lda;                       // weights, no batch
    const float* B = Bg + (size_t)blockIdx.z * sB + n0;           // [K][N]
    float*       C = Cg + (size_t)blockIdx.z * sC;

    // A staging: 1024 16B chunks (rows m, 128B each)
    size_t   gAoff[4];
    uint32_t sAoff[4];
#pragma unroll
    for (int j = 0; j < 4; j++) {
        int id = tid + 256 * j;
        int r  = id >> 3, c4 = id & 7;
        gAoff[j] = (size_t)r * lda + c4 * 4;
        sAoff[j] = r * 128 + ((c4 ^ (r & 7)) << 4);
    }
    // B staging: 2048 16B chunks (32 k-rows x 1024B)
    size_t   gBoff[8];
    uint32_t sBoff[8];
#pragma unroll
    for (int j = 0; j < 8; j++) {
        int id = tid + 256 * j;
        int kr = id >> 6, c4 = id & 63;
        gBoff[j] = (size_t)kr * ldb + c4 * 4;
        sBoff[j] = 16384 + kr * 1024 + (((uint32_t)c4 << 4) ^ ((uint32_t)(kr & 3) << 5));
    }
    const int KT = K >> 5;

#define BISSUE(it_) do {                                                 \
        int s_ = (it_) % BNST;                                           \
        uint32_t base_ = sbase + s_ * BSTG;                              \
        const float* Ai_ = A + (size_t)(it_) * 32;                       \
        const float* Bi_ = B + (size_t)(it_) * 32 * ldb;                 \
        _Pragma("unroll")                                                \
        for (int j = 0; j < 4; j++) CP_ASYNC16(base_ + sAoff[j], Ai_ + gAoff[j]); \
        _Pragma("unroll")                                                \
        for (int j = 0; j < 8; j++) CP_ASYNC16(base_ + sBoff[j], Bi_ + gBoff[j]); \
    } while (0)

    BISSUE(0); CP_COMMIT();
    BISSUE(1); CP_COMMIT();

    float acc[4][8][4];
#pragma unroll
    for (int mi = 0; mi < 4; mi++)
#pragma unroll
        for (int ni = 0; ni < 8; ni++)
#pragma unroll
            for (int r = 0; r < 4; r++) acc[mi][ni][r] = 0.f;

    uint32_t aBase[4], bnOff[8];
    const uint32_t swz = (uint32_t)(mq << 5);
#pragma unroll
    for (int mi = 0; mi < 4; mi++)
        aBase[mi] = (wm * 64 + mi * 16 + q) * 128 + mq * 4;
#pragma unroll
    for (int ni = 0; ni < 8; ni++)
        bnOff[ni] = ((uint32_t)((wn * 64 + ni * 8 + q) * 4)) ^ swz;

    for (int it = 0; it < KT; ++it) {
        CP_WAIT1();
        __syncthreads();
        if (it + 2 < KT) BISSUE(it + 2);
        CP_COMMIT();

        const uint32_t buf = sbase + (it % BNST) * BSTG;
#pragma unroll
        for (int ki = 0; ki < 4; ki++) {
            uint32_t a[4][4], b[8][2];
            const uint32_t c0 = (uint32_t)(((2 * ki) ^ q) << 4);
            const uint32_t c1 = (uint32_t)(((2 * ki + 1) ^ q) << 4);
#pragma unroll
            for (int mi = 0; mi < 4; mi++) {
                uint32_t ad = buf + aBase[mi];
                a[mi][0] = lds32(ad + c0);
                a[mi][1] = lds32(ad + 1024 + c0);
                a[mi][2] = lds32(ad + c1);
                a[mi][3] = lds32(ad + 1024 + c1);
            }
            const uint32_t kB0 = buf + 16384 + (8 * ki + mq) * 1024;
#pragma unroll
            for (int ni = 0; ni < 8; ni++) {
                b[ni][0] = lds32(kB0 + bnOff[ni]);
                b[ni][1] = lds32(kB0 + 4096 + bnOff[ni]);
            }
#pragma unroll
            for (int ni = 0; ni < 8; ni++) { cvt_frag(b[ni][0]); cvt_frag(b[ni][1]); }
#pragma unroll
            for (int mi = 0; mi < 4; mi++)
#pragma unroll
                for (int ni = 0; ni < 8; ni++)
                    mma_tf32(acc[mi][ni], a[mi], b[ni]);
        }
    }
#undef BISSUE

#pragma unroll
    for (int mi = 0; mi < 4; mi++) {
        const int row = m0 + wm * 64 + mi * 16 + q;
        float bm0 = __ldg(bias + row);
        float bm8 = __ldg(bias + row + 8);
#pragma unroll
        for (int ni = 0; ni < 8; ni++) {
            const int col = n0 + wn * 64 + ni * 8 + 2 * mq;
            float v00 = to_tf32(acc[mi][ni][0] + bm0);
            float v01 = to_tf32(acc[mi][ni][1] + bm0);
            float v10 = to_tf32(acc[mi][ni][2] + bm8);
            float v11 = to_tf32(acc[mi][ni][3] + bm8);
            *(float2*)(C + (size_t)row * ldc + col)       = make_float2(v00, v01);
            *(float2*)(C + (size_t)(row + 8) * ldc + col) = make_float2(v10, v11);
        }
    }
}

// ---------------- fused prepass kernels ----------------
// dual transpose: z=0 -> ln_w, z=1 -> ln_b; (LAT,S) -> (S,LAT)
__global__ __launch_bounds__(256)
void transpose2_kernel(const float* __restrict__ w, const float* __restrict__ b,
                       float* __restrict__ ow, float* __restrict__ ob)
{
    __shared__ float t[32][33];
    const float* in  = blockIdx.z ? b : w;
    float*       out = blockIdx.z ? ob : ow;
    int c = blockIdx.x * 32 + threadIdx.x;
#pragma unroll
    for (int i = 0; i < 4; i++) {
        int r = blockIdx.y * 32 + threadIdx.y + i * 8;
        t[threadIdx.y + i * 8][threadIdx.x] = in[(size_t)r * S_ + c];
    }
    __syncthreads();
    int r2 = blockIdx.y * 32 + threadIdx.x;
#pragma unroll
    for (int i = 0; i < 4; i++) {
        int c2 = blockIdx.x * 32 + threadIdx.y + i * 8;
        out[(size_t)c2 * LAT_ + r2] = t[threadIdx.x][threadIdx.y + i * 8];
    }
}

// 4-way tf32 round copy: each segment 512*2048 floats = 262144 float4
__global__ __launch_bounds__(256)
void round_copy4_kernel(const float* __restrict__ i0, const float* __restrict__ i1,
                        const float* __restrict__ i2, const float* __restrict__ i3,
                        float* __restrict__ o0, float* __restrict__ o1,
                        float* __restrict__ o2, float* __restrict__ o3)
{
    size_t idx = (size_t)blockIdx.x * blockDim.x + threadIdx.x;   // 0..1048575
    int seg    = (int)(idx >> 18);
    size_t loc = idx & 262143;
    const float* in; float* out;
    if      (seg == 0) { in = i0; out = o0; }
    else if (seg == 1) { in = i1; out = o1; }
    else if (seg == 2) { in = i2; out = o2; }
    else               { in = i3; out = o3; }
    float4 v = ((const float4*)in)[loc];
    v.x = to_tf32(v.x); v.y = to_tf32(v.y); v.z = to_tf32(v.z); v.w = to_tf32(v.w);
    ((float4*)out)[loc] = v;
}

__global__ void stack_bias_kernel(const float* __restrict__ b0, const float* __restrict__ b1,
                                  float* __restrict__ out)
{
    int i = threadIdx.x + blockIdx.x * blockDim.x;
    out[i] = (i < 512) ? b0[i] : b1[i - 512];
}

// ---------------- softmax over L=2048 ----------------
__global__ __launch_bounds__(256)
void softmax_kernel(float* __restrict__ sc)
{
    float* p = sc + (size_t)blockIdx.x * L_;
    const int tid = threadIdx.x;
    float v[8];
    float mx = -1e30f;
#pragma unroll
    for (int i = 0; i < 8; i++) { v[i] = p[tid + i * 256]; mx = fmaxf(mx, v[i]); }
#pragma unroll
    for (int o = 16; o; o >>= 1) mx = fmaxf(mx, __shfl_xor_sync(0xffffffffu, mx, o));
    __shared__ float smax[8], ssum[8];
    if ((tid & 31) == 0) smax[tid >> 5] = mx;
    __syncthreads();
    float m2 = smax[0];
#pragma unroll
    for (int i = 1; i < 8; i++) m2 = fmaxf(m2, smax[i]);
    float s = 0.f;
#pragma unroll
    for (int i = 0; i < 8; i++) { v[i] = __expf(v[i] - m2); s += v[i]; }
#pragma unroll
    for (int o = 16; o; o >>= 1) s += __shfl_xor_sync(0xffffffffu, s, o);
    if ((tid & 31) == 0) ssum[tid >> 5] = s;
    __syncthreads();
    float tot = 0.f;
#pragma unroll
    for (int i = 0; i < 8; i++) tot += ssum[i];
    float inv = 1.f / tot;
#pragma unroll
    for (int i = 0; i < 8; i++) p[tid + i * 256] = to_tf32(v[i] * inv);
}

// ---------------- layernorm stats (two-phase) ----------------
__global__ __launch_bounds__(256)
void ln_part_kernel(const float* __restrict__ x, float2* __restrict__ part)
{
    const int batch = blockIdx.y;
    const int p     = blockIdx.x;
    const float4* xb = (const float4*)(x + (size_t)batch * (LAT_ * S_) + p * 16384);
    float s = 0.f, ss = 0.f;
#pragma unroll
    for (int i = 0; i < 16; i++) {
        float4 v = xb[threadIdx.x + i * 256];
        s  += v.x + v.y + v.z + v.w;
        ss += v.x * v.x + v.y * v.y + v.z * v.z + v.w * v.w;
    }
#pragma unroll
    for (int o = 16; o; o >>= 1) {
        s  += __shfl_xor_sync(0xffffffffu, s, o);
        ss += __shfl_xor_sync(0xffffffffu, ss, o);
    }
    __shared__ float rs[8], rss[8];
    if ((threadIdx.x & 31) == 0) { rs[threadIdx.x >> 5] = s; rss[threadIdx.x >> 5] = ss; }
    __syncthreads();
    if (threadIdx.x == 0) {
        float S = 0.f, SSq = 0.f;
#pragma unroll
        for (int i = 0; i < 8; i++) { S += rs[i]; SSq += rss[i]; }
        part[batch * 16 + p] = make_float2(S, SSq);
    }
}

__global__ void ln_final_kernel(const float2* __restrict__ part, float* __restrict__ stats)
{
    int b = threadIdx.x;
    float S = 0.f, SSq = 0.f;
#pragma unroll
    for (int i = 0; i < 16; i++) {
        float2 v = part[b * 16 + i];
        S += v.x; SSq += v.y;
    }
    const float invN = 1.f / (float)(LAT_ * S_);
    float mu  = S * invN;
    float var = SSq * invN - mu * mu;
    stats[b * 2 + 0] = mu;
    stats[b * 2 + 1] = rsqrtf(var + 1e-5f);
}

// ---------------- normalize + affine + relu ----------------
__global__ __launch_bounds__(256)
void norm_relu_kernel(const float* __restrict__ attn, const float* __restrict__ lnw,
                      const float* __restrict__ lnb, const float* __restrict__ stats,
                      float* __restrict__ out)
{
    size_t i4 = (size_t)blockIdx.x * blockDim.x + threadIdx.x;
    int n  = (int)(i4 >> 16);
    int cs = (int)(i4 & 65535);
    float mu = stats[n * 2 + 0];
    float r  = stats[n * 2 + 1];
    float4 x = ((const float4*)attn)[i4];
    float4 w = ((const float4*)lnw)[cs];
    float4 b = ((const float4*)lnb)[cs];
    float4 y;
    y.x = to_tf32(fmaxf(fmaf((x.x - mu) * r, w.x, b.x), 0.f));
    y.y = to_tf32(fmaxf(fmaf((x.y - mu) * r, w.y, b.y), 0.f));
    y.z = to_tf32(fmaxf(fmaf((x.z - mu) * r, w.z, b.z), 0.f));
    y.w = to_tf32(fmaxf(fmaf((x.w - mu) * r, w.w, b.w), 0.f));
    ((float4*)out)[i4] = y;
}

// ---------------- launch ----------------
extern "C" void kernel_launch(void* const* d_in, const int* in_sizes, int n_in,
                              void* d_out, int out_size)
{
    const float* st    = (const float*)d_in[0];
    const float* lt    = (const float*)d_in[1];
    const float* w_st  = (const float*)d_in[2];
    const float* b_st  = (const float*)d_in[3];
    const float* w_lt  = (const float*)d_in[4];
    const float* b_lt  = (const float*)d_in[5];
    const float* w_g   = (const float*)d_in[6];
    const float* b_g   = (const float*)d_in[7];
    const float* ln_w  = (const float*)d_in[8];
    const float* ln_b  = (const float*)d_in[9];
    const float* w_out = (const float*)d_in[10];
    const float* b_out = (const float*)d_in[11];
    float* out = (float*)d_out;

    float *thetaT, *pg, *sc, *attnT, *nrmT, *lnTw, *lnTb, *stats;
    float *wstR, *wLG, *bLG, *woutR;
    float2 *part;
    cudaGetSymbolAddress((void**)&thetaT, g_thetaT);
    cudaGetSymbolAddress((void**)&pg,     g_pg);
    cudaGetSymbolAddress((void**)&sc,     g_sc);
    cudaGetSymbolAddress((void**)&attnT,  g_attnT);
    cudaGetSymbolAddress((void**)&nrmT,   g_nrmT);
    cudaGetSymbolAddress((void**)&lnTw,   g_lnTw);
    cudaGetSymbolAddress((void**)&lnTb,   g_lnTb);
    cudaGetSymbolAddress((void**)&part,   g_part);
    cudaGetSymbolAddress((void**)&stats,  g_stats);
    cudaGetSymbolAddress((void**)&wstR,   g_wstR);
    cudaGetSymbolAddress((void**)&wLG,    g_wLG);
    cudaGetSymbolAddress((void**)&bLG,    g_bLG);
    cudaGetSymbolAddress((void**)&woutR,  g_woutR);

    cudaFuncSetAttribute(gemm_mma<1,0,1,0>, cudaFuncAttributeMaxDynamicSharedMemorySize, GEMM_SMEM);
    cudaFuncSetAttribute(gemm_mma<0,1,0,0>, cudaFuncAttributeMaxDynamicSharedMemorySize, GEMM_SMEM);
    cudaFuncSetAttribute(gemm_mma<0,0,0,0>, cudaFuncAttributeMaxDynamicSharedMemorySize, GEMM_SMEM);
    cudaFuncSetAttribute(gemm_big, cudaFuncAttributeMaxDynamicSharedMemorySize, GEMM_BIG_SMEM);

    const float inv_sqrt_lat = 0.044194173824159216f;   // 1/sqrt(512)

    // fused pre-pass: 3 launches
    transpose2_kernel<<<dim3(S_ / 32, LAT_ / 32, 2), dim3(32, 8)>>>(ln_w, ln_b, lnTw, lnTb);
    round_copy4_kernel<<<4096, 256>>>(w_st, w_lt, w_g, w_out,
                                      wstR, wLG, wLG + (size_t)512 * C_LT_, woutR);
    stack_bias_kernel<<<4, 256>>>(b_lt, b_g, bLG);

    // 1) thetaT[s][o] = sum_c st[c][s] * w_st[o][c] + b_st[o]    (A transposed, round A)
    gemm_mma<1,0,1,0><<<dim3(LAT_ / 128, S_ / 128, NBATCH), 256, GEMM_SMEM>>>(
        st, wstR, thetaT, b_st, C_ST_, S_, C_ST_, LAT_,
        (size_t)C_ST_ * S_, 0, (size_t)S_ * LAT_, 1.f, 1, 1);

    // 2) merged phi+g (big-tile): pg[o2][l] = sum_c wLG[o2][c] * lt[c][l] + bLG[o2]
    gemm_big<<<dim3(L_ / 256, 1024 / 128, NBATCH), 256, GEMM_BIG_SMEM>>>(
        wLG, lt, pg, bLG, C_LT_, C_LT_, L_, L_,
        (size_t)C_LT_ * L_, (size_t)1024 * L_);

    // 3) scores[s][l] = (1/sqrt(LAT)) * sum_o thetaT[s][o] * phi[o][l]   (B transposed)
    gemm_mma<0,1,0,0><<<dim3(L_ / 128, S_ / 128, NBATCH), 256, GEMM_SMEM>>>(
        thetaT, pg, sc, nullptr, LAT_, LAT_, L_, L_,
        (size_t)S_ * LAT_, (size_t)1024 * L_, (size_t)S_ * L_, inv_sqrt_lat, 0, 0);

    // 4) softmax over L (in place, rounded output)
    softmax_kernel<<<NBATCH * S_, 256>>>(sc);

    // 5) attnT[s][c] = sum_l p[s][l] * g[c][l]
    gemm_mma<0,0,0,0><<<dim3(LAT_ / 128, S_ / 128, NBATCH), 256, GEMM_SMEM>>>(
        sc, pg + (size_t)512 * L_, attnT, nullptr, L_, L_, L_, LAT_,
        (size_t)S_ * L_, (size_t)1024 * L_, (size_t)S_ * LAT_, 1.f, 0, 0);

    // 6) layernorm stats (two-phase) + normalize + relu
    ln_part_kernel<<<dim3(16, NBATCH), 256>>>(attnT, part);
    ln_final_kernel<<<1, 32>>>(part, stats);
    norm_relu_kernel<<<(NBATCH * LAT_ * S_ / 4) / 256, 256>>>(attnT, lnTw, lnTb, stats, nrmT);

    // 7) out[o][s] = sum_c w_out[o][c] * nrmT[s][c] + b_out[o]
    gemm_mma<0,0,0,0><<<dim3(S_ / 128, C_ST_ / 128, NBATCH), 256, GEMM_SMEM>>>(
        woutR, nrmT, out, b_out, LAT_, LAT_, LAT_, S_,
        0, (size_t)S_ * LAT_, (size_t)C_ST_ * S_, 1.f, 2, 0);
}

// round 14
// speedup vs baseline: 4.3159x; 1.0400x over previous
#include <cuda_runtime.h>
#include <cstdint>
#include <math.h>

#define NBATCH 32
#define C_ST_  2048
#define C_LT_  2048
#define LAT_   512
#define S_     512
#define L_     2048

// ---------------- scratch (__device__ globals; no allocation) ----------------
__device__ float g_thetaT[(size_t)NBATCH * S_ * LAT_];    // (n, S, LAT)   tf32-rounded
__device__ float g_pg   [(size_t)NBATCH * 1024 * L_];     // (n, 1024, L): rows 0..511 phi, 512..1023 g
__device__ float g_sc   [(size_t)NBATCH * S_ * L_];       // (n, S, L)
__device__ float g_attnT[(size_t)NBATCH * S_ * LAT_];     // (n, S, LAT)
__device__ float g_nrmT [(size_t)NBATCH * S_ * LAT_];     // (n, S, LAT)   tf32-rounded
__device__ float g_lnTw [(size_t)S_ * LAT_];
__device__ float g_lnTb [(size_t)S_ * LAT_];
__device__ float2 g_part[NBATCH * 16];
__device__ float g_stats[NBATCH * 2];
__device__ float g_wstR [(size_t)LAT_ * C_ST_];           // tf32-rounded weights
__device__ float g_wLG  [(size_t)1024 * C_LT_];           // stacked [w_lt; w_g], tf32-rounded
__device__ float g_bLG  [1024];                           // stacked [b_lt; b_g]
__device__ float g_woutR[(size_t)C_ST_ * LAT_];

// ---------------- helpers ----------------
__device__ __forceinline__ uint32_t smem_u32(const void* p) {
    uint32_t a;
    asm("{ .reg .u64 t; cvta.to.shared.u64 t, %1; cvt.u32.u64 %0, t; }" : "=r"(a) : "l"(p));
    return a;
}
__device__ __forceinline__ float to_tf32(float x) {
    float y;
    asm("cvt.rna.tf32.f32 %0, %1;" : "=f"(y) : "f"(x));
    return y;
}
__device__ __forceinline__ void cvt_frag(uint32_t& u) {
    float f = __uint_as_float(u);
    u = __float_as_uint(to_tf32(f));
}
#define CP_ASYNC16(dst, src) \
    asm volatile("cp.async.cg.shared.global [%0], [%1], 16;" :: "r"(dst), "l"(src))
#define CP_COMMIT() asm volatile("cp.async.commit_group;")
#define CP_WAIT1()  asm volatile("cp.async.wait_group 1;")
#define CP_WAIT2()  asm volatile("cp.async.wait_group 2;")

__device__ __forceinline__ uint32_t lds32(uint32_t addr) {
    uint32_t v;
    asm volatile("ld.shared.b32 %0, [%1];" : "=r"(v) : "r"(addr));
    return v;
}
__device__ __forceinline__ void mma_tf32(float* d, const uint32_t* a, const uint32_t* b) {
    asm volatile(
        "mma.sync.aligned.m16n8k8.row.col.f32.tf32.tf32.f32 "
        "{%0,%1,%2,%3},{%4,%5,%6,%7},{%8,%9},{%0,%1,%2,%3};"
        : "+f"(d[0]), "+f"(d[1]), "+f"(d[2]), "+f"(d[3])
        : "r"(a[0]), "r"(a[1]), "r"(a[2]), "r"(a[3]), "r"(b[0]), "r"(b[1]));
}

// ================= generic 128x128x32 GEMM (HW-validated) =================
#define NST 3
#define STAGE_BYTES 32768
#define GEMM_SMEM (NST * STAGE_BYTES)     // 96 KB

template <int ATR, int BTR, int RA, int RB>
__global__ __launch_bounds__(256, 2)
void gemm_mma(const float* __restrict__ Ag, const float* __restrict__ Bg,
              float* __restrict__ Cg, const float* __restrict__ bias,
              int K, int lda, int ldb, int ldc,
              size_t sA, size_t sB, size_t sC, float alpha,
              int bias_mode, int round_out)
{
    extern __shared__ char smem[];
    const uint32_t sbase = smem_u32(smem);
    const int tid  = threadIdx.x;
    const int wid  = tid >> 5;
    const int lane = tid & 31;
    const int q    = lane >> 2;
    const int mq   = lane & 3;
    const int wm   = wid >> 2;
    const int wn   = wid & 3;
    const int m0   = blockIdx.y * 128;
    const int n0   = blockIdx.x * 128;

    const float* A = Ag + (size_t)blockIdx.z * sA + (ATR ? (size_t)m0 : (size_t)m0 * lda);
    const float* B = Bg + (size_t)blockIdx.z * sB + (BTR ? (size_t)n0 : (size_t)n0 * ldb);
    float*       C = Cg + (size_t)blockIdx.z * sC;

    size_t   gAoff[4], gBoff[4];
    uint32_t sAoff[4], sBoff[4];
#pragma unroll
    for (int j = 0; j < 4; j++) {
        int id = tid + 256 * j;
        if (ATR) {
            int kr = id >> 5, c4 = id & 31;
            gAoff[j] = (size_t)kr * lda + c4 * 4;
            sAoff[j] = kr * 512 + ((c4 * 16) ^ ((kr & 3) << 5));
        } else {
            int r = id >> 3, c4 = id & 7;
            gAoff[j] = (size_t)r * lda + c4 * 4;
            sAoff[j] = r * 128 + ((c4 ^ (r & 7)) << 4);
        }
        if (BTR) {
            int kr = id >> 5, c4 = id & 31;
            gBoff[j] = (size_t)kr * ldb + c4 * 4;
            sBoff[j] = 16384 + kr * 512 + ((c4 * 16) ^ ((kr & 3) << 5));
        } else {
            int r = id >> 3, c4 = id & 7;
            gBoff[j] = (size_t)r * ldb + c4 * 4;
            sBoff[j] = 16384 + r * 128 + ((c4 ^ (r & 7)) << 4);
        }
    }
    const size_t aAdv = ATR ? (size_t)32 * lda : (size_t)32;
    const size_t bAdv = BTR ? (size_t)32 * ldb : (size_t)32;
    const int KT = K >> 5;

#define ISSUE(it_) do {                                                  \
        int s_ = (it_) % NST;                                            \
        uint32_t base_ = sbase + s_ * STAGE_BYTES;                       \
        const float* Ai_ = A + (size_t)(it_) * aAdv;                     \
        const float* Bi_ = B + (size_t)(it_) * bAdv;                     \
        _Pragma("unroll")                                                \
        for (int j = 0; j < 4; j++) {                                    \
            CP_ASYNC16(base_ + sAoff[j], Ai_ + gAoff[j]);                \
            CP_ASYNC16(base_ + sBoff[j], Bi_ + gBoff[j]);                \
        }                                                                \
    } while (0)

    ISSUE(0); CP_COMMIT();
    ISSUE(1); CP_COMMIT();

    float acc[4][4][4];
#pragma unroll
    for (int mi = 0; mi < 4; mi++)
#pragma unroll
        for (int ni = 0; ni < 4; ni++)
#pragma unroll
            for (int r = 0; r < 4; r++) acc[mi][ni][r] = 0.f;

    uint32_t aBase[4], bBase[4];
    uint32_t amLo[4], amHi[4];
    uint32_t bnLo[4];
    const uint32_t swz = (uint32_t)(mq << 5);
#pragma unroll
    for (int mi = 0; mi < 4; mi++) {
        int m = wm * 64 + mi * 16 + q;
        aBase[mi] = m * 128 + mq * 4;
        amLo[mi]  = ((uint32_t)(m * 4)) ^ swz;
        amHi[mi]  = ((uint32_t)((m + 8) * 4)) ^ swz;
    }
#pragma unroll
    for (int ni = 0; ni < 4; ni++) {
        int n = wn * 32 + ni * 8 + q;
        bBase[ni] = n * 128 + mq * 4 + 16384;
        bnLo[ni]  = ((uint32_t)(n * 4)) ^ swz;
    }

    for (int it = 0; it < KT; ++it) {
        CP_WAIT1();
        __syncthreads();
        if (it + 2 < KT) ISSUE(it + 2);
        CP_COMMIT();

        const uint32_t buf = sbase + (it % NST) * STAGE_BYTES;
#pragma unroll
        for (int ki = 0; ki < 4; ki++) {
            uint32_t a[4][4], b[4][2];
            if (ATR) {
                const uint32_t kA = buf + ki * 4096 + mq * 512;
#pragma unroll
                for (int mi = 0; mi < 4; mi++) {
                    a[mi][0] = lds32(kA + amLo[mi]);
                    a[mi][1] = lds32(kA + amHi[mi]);
                    a[mi][2] = lds32(kA + 2048 + amLo[mi]);
                    a[mi][3] = lds32(kA + 2048 + amHi[mi]);
                }
            } else {
                const uint32_t c0 = (uint32_t)(((2 * ki) ^ q) << 4);
                const uint32_t c1 = (uint32_t)(((2 * ki + 1) ^ q) << 4);
#pragma unroll
                for (int mi = 0; mi < 4; mi++) {
                    uint32_t ad = buf + aBase[mi];
                    a[mi][0] = lds32(ad + c0);
                    a[mi][1] = lds32(ad + 1024 + c0);
                    a[mi][2] = lds32(ad + c1);
                    a[mi][3] = lds32(ad + 1024 + c1);
                }
            }
            if (BTR) {
                const uint32_t kB = buf + 16384 + ki * 4096 + mq * 512;
#pragma unroll
                for (int ni = 0; ni < 4; ni++) {
                    b[ni][0] = lds32(kB + bnLo[ni]);
                    b[ni][1] = lds32(kB + 2048 + bnLo[ni]);
                }
            } else {
                const uint32_t c0 = (uint32_t)(((2 * ki) ^ q) << 4);
                const uint32_t c1 = (uint32_t)(((2 * ki + 1) ^ q) << 4);
#pragma unroll
                for (int ni = 0; ni < 4; ni++) {
                    uint32_t bd = buf + bBase[ni];
                    b[ni][0] = lds32(bd + c0);
                    b[ni][1] = lds32(bd + c1);
                }
            }
            if (RA) {
#pragma unroll
                for (int mi = 0; mi < 4; mi++)
#pragma unroll
                    for (int r = 0; r < 4; r++) cvt_frag(a[mi][r]);
            }
            if (RB) {
#pragma unroll
                for (int ni = 0; ni < 4; ni++) { cvt_frag(b[ni][0]); cvt_frag(b[ni][1]); }
            }
#pragma unroll
            for (int mi = 0; mi < 4; mi++)
#pragma unroll
                for (int ni = 0; ni < 4; ni++)
                    mma_tf32(acc[mi][ni], a[mi], b[ni]);
        }
    }
#undef ISSUE

#pragma unroll
    for (int mi = 0; mi < 4; mi++) {
        const int row = m0 + wm * 64 + mi * 16 + q;
        float bm0 = 0.f, bm8 = 0.f;
        if (bias_mode == 2) { bm0 = __ldg(bias + row); bm8 = __ldg(bias + row + 8); }
#pragma unroll
        for (int ni = 0; ni < 4; ni++) {
            const int col = n0 + wn * 32 + ni * 8 + 2 * mq;
            float bn0 = 0.f, bn1 = 0.f;
            if (bias_mode == 1) { bn0 = __ldg(bias + col); bn1 = __ldg(bias + col + 1); }
            float v00 = acc[mi][ni][0] * alpha;
            float v01 = acc[mi][ni][1] * alpha;
            float v10 = acc[mi][ni][2] * alpha;
            float v11 = acc[mi][ni][3] * alpha;
            if (bias_mode == 1) { v00 += bn0; v01 += bn1; v10 += bn0; v11 += bn1; }
            else if (bias_mode == 2) { v00 += bm0; v01 += bm0; v10 += bm8; v11 += bm8; }
            if (round_out) {
                v00 = to_tf32(v00); v01 = to_tf32(v01);
                v10 = to_tf32(v10); v11 = to_tf32(v11);
            }
            *(float2*)(C + (size_t)row * ldc + col)       = make_float2(v00, v01);
            *(float2*)(C + (size_t)(row + 8) * ldc + col) = make_float2(v10, v11);
        }
    }
}

// ================= big-tile GEMM: 128m x 256n x 32k, D = alpha*A@B (+row bias) ======
// A: [M][K] k-contig (batch stride sA). B: [K][N] n-contig (batch stride sB).
// RBC: cvt.rna B fragments (raw fp32 input). 4 stages, prefetch depth 3 (1 CTA/SM).
#define BNST 4
#define BSTG (16384 + 32768)            // A 16KB + B 32KB = 48KB/stage
#define GEMM_BIG_SMEM (BNST * BSTG)     // 192 KB

template <int RBC>
__global__ __launch_bounds__(256, 1)
void gemm_big(const float* __restrict__ Ag, const float* __restrict__ Bg,
              float* __restrict__ Cg, const float* __restrict__ bias,
              int K, int lda, int ldb, int ldc,
              size_t sA, size_t sB, size_t sC, float alpha, int round_out)
{
    extern __shared__ char smem[];
    const uint32_t sbase = smem_u32(smem);
    const int tid  = threadIdx.x;
    const int wid  = tid >> 5;
    const int lane = tid & 31;
    const int q    = lane >> 2;
    const int mq   = lane & 3;
    const int wm   = wid >> 2;        // 0..1
    const int wn   = wid & 3;         // 0..3
    const int m0   = blockIdx.y * 128;
    const int n0   = blockIdx.x * 256;

    const float* A = Ag + (size_t)blockIdx.z * sA + (size_t)m0 * lda;
    const float* B = Bg + (size_t)blockIdx.z * sB + n0;
    float*       C = Cg + (size_t)blockIdx.z * sC;

    size_t   gAoff[4];
    uint32_t sAoff[4];
#pragma unroll
    for (int j = 0; j < 4; j++) {
        int id = tid + 256 * j;
        int r  = id >> 3, c4 = id & 7;
        gAoff[j] = (size_t)r * lda + c4 * 4;
        sAoff[j] = r * 128 + ((c4 ^ (r & 7)) << 4);
    }
    size_t   gBoff[8];
    uint32_t sBoff[8];
#pragma unroll
    for (int j = 0; j < 8; j++) {
        int id = tid + 256 * j;
        int kr = id >> 6, c4 = id & 63;
        gBoff[j] = (size_t)kr * ldb + c4 * 4;
        sBoff[j] = 16384 + kr * 1024 + (((uint32_t)c4 << 4) ^ ((uint32_t)(kr & 3) << 5));
    }
    const int KT = K >> 5;

#define BISSUE(it_) do {                                                 \
        int s_ = (it_) % BNST;                                           \
        uint32_t base_ = sbase + s_ * BSTG;                              \
        const float* Ai_ = A + (size_t)(it_) * 32;                       \
        const float* Bi_ = B + (size_t)(it_) * 32 * ldb;                 \
        _Pragma("unroll")                                                \
        for (int j = 0; j < 4; j++) CP_ASYNC16(base_ + sAoff[j], Ai_ + gAoff[j]); \
        _Pragma("unroll")                                                \
        for (int j = 0; j < 8; j++) CP_ASYNC16(base_ + sBoff[j], Bi_ + gBoff[j]); \
    } while (0)

    BISSUE(0); CP_COMMIT();
    BISSUE(1); CP_COMMIT();
    BISSUE(2); CP_COMMIT();

    float acc[4][8][4];
#pragma unroll
    for (int mi = 0; mi < 4; mi++)
#pragma unroll
        for (int ni = 0; ni < 8; ni++)
#pragma unroll
            for (int r = 0; r < 4; r++) acc[mi][ni][r] = 0.f;

    uint32_t aBase[4], bnOff[8];
    const uint32_t swz = (uint32_t)(mq << 5);
#pragma unroll
    for (int mi = 0; mi < 4; mi++)
        aBase[mi] = (wm * 64 + mi * 16 + q) * 128 + mq * 4;
#pragma unroll
    for (int ni = 0; ni < 8; ni++)
        bnOff[ni] = ((uint32_t)((wn * 64 + ni * 8 + q) * 4)) ^ swz;

    for (int it = 0; it < KT; ++it) {
        CP_WAIT2();
        __syncthreads();
        if (it + 3 < KT) BISSUE(it + 3);
        CP_COMMIT();

        const uint32_t buf = sbase + (it % BNST) * BSTG;
#pragma unroll
        for (int ki = 0; ki < 4; ki++) {
            uint32_t a[4][4], b[8][2];
            const uint32_t c0 = (uint32_t)(((2 * ki) ^ q) << 4);
            const uint32_t c1 = (uint32_t)(((2 * ki + 1) ^ q) << 4);
#pragma unroll
            for (int mi = 0; mi < 4; mi++) {
                uint32_t ad = buf + aBase[mi];
                a[mi][0] = lds32(ad + c0);
                a[mi][1] = lds32(ad + 1024 + c0);
                a[mi][2] = lds32(ad + c1);
                a[mi][3] = lds32(ad + 1024 + c1);
            }
            const uint32_t kB0 = buf + 16384 + (8 * ki + mq) * 1024;
#pragma unroll
            for (int ni = 0; ni < 8; ni++) {
                b[ni][0] = lds32(kB0 + bnOff[ni]);
                b[ni][1] = lds32(kB0 + 4096 + bnOff[ni]);
            }
            if (RBC) {
#pragma unroll
                for (int ni = 0; ni < 8; ni++) { cvt_frag(b[ni][0]); cvt_frag(b[ni][1]); }
            }
#pragma unroll
            for (int mi = 0; mi < 4; mi++)
#pragma unroll
                for (int ni = 0; ni < 8; ni++)
                    mma_tf32(acc[mi][ni], a[mi], b[ni]);
        }
    }
#undef BISSUE

#pragma unroll
    for (int mi = 0; mi < 4; mi++) {
        const int row = m0 + wm * 64 + mi * 16 + q;
        float bm0 = 0.f, bm8 = 0.f;
        if (bias) { bm0 = __ldg(bias + row); bm8 = __ldg(bias + row + 8); }
#pragma unroll
        for (int ni = 0; ni < 8; ni++) {
            const int col = n0 + wn * 64 + ni * 8 + 2 * mq;
            float v00 = acc[mi][ni][0] * alpha + bm0;
            float v01 = acc[mi][ni][1] * alpha + bm0;
            float v10 = acc[mi][ni][2] * alpha + bm8;
            float v11 = acc[mi][ni][3] * alpha + bm8;
            if (round_out) {
                v00 = to_tf32(v00); v01 = to_tf32(v01);
                v10 = to_tf32(v10); v11 = to_tf32(v11);
            }
            *(float2*)(C + (size_t)row * ldc + col)       = make_float2(v00, v01);
            *(float2*)(C + (size_t)(row + 8) * ldc + col) = make_float2(v10, v11);
        }
    }
}

// ---------------- fused prepass kernels ----------------
__global__ __launch_bounds__(256)
void transpose2_kernel(const float* __restrict__ w, const float* __restrict__ b,
                       float* __restrict__ ow, float* __restrict__ ob)
{
    __shared__ float t[32][33];
    const float* in  = blockIdx.z ? b : w;
    float*       out = blockIdx.z ? ob : ow;
    int c = blockIdx.x * 32 + threadIdx.x;
#pragma unroll
    for (int i = 0; i < 4; i++) {
        int r = blockIdx.y * 32 + threadIdx.y + i * 8;
        t[threadIdx.y + i * 8][threadIdx.x] = in[(size_t)r * S_ + c];
    }
    __syncthreads();
    int r2 = blockIdx.y * 32 + threadIdx.x;
#pragma unroll
    for (int i = 0; i < 4; i++) {
        int c2 = blockIdx.x * 32 + threadIdx.y + i * 8;
        out[(size_t)c2 * LAT_ + r2] = t[threadIdx.x][threadIdx.y + i * 8];
    }
}

__global__ __launch_bounds__(256)
void round_copy4_kernel(const float* __restrict__ i0, const float* __restrict__ i1,
                        const float* __restrict__ i2, const float* __restrict__ i3,
                        float* __restrict__ o0, float* __restrict__ o1,
                        float* __restrict__ o2, float* __restrict__ o3)
{
    size_t idx = (size_t)blockIdx.x * blockDim.x + threadIdx.x;
    int seg    = (int)(idx >> 18);
    size_t loc = idx & 262143;
    const float* in; float* out;
    if      (seg == 0) { in = i0; out = o0; }
    else if (seg == 1) { in = i1; out = o1; }
    else if (seg == 2) { in = i2; out = o2; }
    else               { in = i3; out = o3; }
    float4 v = ((const float4*)in)[loc];
    v.x = to_tf32(v.x); v.y = to_tf32(v.y); v.z = to_tf32(v.z); v.w = to_tf32(v.w);
    ((float4*)out)[loc] = v;
}

__global__ void stack_bias_kernel(const float* __restrict__ b0, const float* __restrict__ b1,
                                  float* __restrict__ out)
{
    int i = threadIdx.x + blockIdx.x * blockDim.x;
    out[i] = (i < 512) ? b0[i] : b1[i - 512];
}

// ---------------- softmax over L=2048 ----------------
__global__ __launch_bounds__(256)
void softmax_kernel(float* __restrict__ sc)
{
    float* p = sc + (size_t)blockIdx.x * L_;
    const int tid = threadIdx.x;
    float v[8];
    float mx = -1e30f;
#pragma unroll
    for (int i = 0; i < 8; i++) { v[i] = p[tid + i * 256]; mx = fmaxf(mx, v[i]); }
#pragma unroll
    for (int o = 16; o; o >>= 1) mx = fmaxf(mx, __shfl_xor_sync(0xffffffffu, mx, o));
    __shared__ float smax[8], ssum[8];
    if ((tid & 31) == 0) smax[tid >> 5] = mx;
    __syncthreads();
    float m2 = smax[0];
#pragma unroll
    for (int i = 1; i < 8; i++) m2 = fmaxf(m2, smax[i]);
    float s = 0.f;
#pragma unroll
    for (int i = 0; i < 8; i++) { v[i] = __expf(v[i] - m2); s += v[i]; }
#pragma unroll
    for (int o = 16; o; o >>= 1) s += __shfl_xor_sync(0xffffffffu, s, o);
    if ((tid & 31) == 0) ssum[tid >> 5] = s;
    __syncthreads();
    float tot = 0.f;
#pragma unroll
    for (int i = 0; i < 8; i++) tot += ssum[i];
    float inv = 1.f / tot;
#pragma unroll
    for (int i = 0; i < 8; i++) p[tid + i * 256] = to_tf32(v[i] * inv);
}

// ---------------- layernorm stats (two-phase) ----------------
__global__ __launch_bounds__(256)
void ln_part_kernel(const float* __restrict__ x, float2* __restrict__ part)
{
    const int batch = blockIdx.y;
    const int p     = blockIdx.x;
    const float4* xb = (const float4*)(x + (size_t)batch * (LAT_ * S_) + p * 16384);
    float s = 0.f, ss = 0.f;
#pragma unroll
    for (int i = 0; i < 16; i++) {
        float4 v = xb[threadIdx.x + i * 256];
        s  += v.x + v.y + v.z + v.w;
        ss += v.x * v.x + v.y * v.y + v.z * v.z + v.w * v.w;
    }
#pragma unroll
    for (int o = 16; o; o >>= 1) {
        s  += __shfl_xor_sync(0xffffffffu, s, o);
        ss += __shfl_xor_sync(0xffffffffu, ss, o);
    }
    __shared__ float rs[8], rss[8];
    if ((threadIdx.x & 31) == 0) { rs[threadIdx.x >> 5] = s; rss[threadIdx.x >> 5] = ss; }
    __syncthreads();
    if (threadIdx.x == 0) {
        float S = 0.f, SSq = 0.f;
#pragma unroll
        for (int i = 0; i < 8; i++) { S += rs[i]; SSq += rss[i]; }
        part[batch * 16 + p] = make_float2(S, SSq);
    }
}

__global__ void ln_final_kernel(const float2* __restrict__ part, float* __restrict__ stats)
{
    int b = threadIdx.x;
    float S = 0.f, SSq = 0.f;
#pragma unroll
    for (int i = 0; i < 16; i++) {
        float2 v = part[b * 16 + i];
        S += v.x; SSq += v.y;
    }
    const float invN = 1.f / (float)(LAT_ * S_);
    float mu  = S * invN;
    float var = SSq * invN - mu * mu;
    stats[b * 2 + 0] = mu;
    stats[b * 2 + 1] = rsqrtf(var + 1e-5f);
}

// ---------------- normalize + affine + relu ----------------
__global__ __launch_bounds__(256)
void norm_relu_kernel(const float* __restrict__ attn, const float* __restrict__ lnw,
                      const float* __restrict__ lnb, const float* __restrict__ stats,
                      float* __restrict__ out)
{
    size_t i4 = (size_t)blockIdx.x * blockDim.x + threadIdx.x;
    int n  = (int)(i4 >> 16);
    int cs = (int)(i4 & 65535);
    float mu = stats[n * 2 + 0];
    float r  = stats[n * 2 + 1];
    float4 x = ((const float4*)attn)[i4];
    float4 w = ((const float4*)lnw)[cs];
    float4 b = ((const float4*)lnb)[cs];
    float4 y;
    y.x = to_tf32(fmaxf(fmaf((x.x - mu) * r, w.x, b.x), 0.f));
    y.y = to_tf32(fmaxf(fmaf((x.y - mu) * r, w.y, b.y), 0.f));
    y.z = to_tf32(fmaxf(fmaf((x.z - mu) * r, w.z, b.z), 0.f));
    y.w = to_tf32(fmaxf(fmaf((x.w - mu) * r, w.w, b.w), 0.f));
    ((float4*)out)[i4] = y;
}

// ---------------- launch ----------------
extern "C" void kernel_launch(void* const* d_in, const int* in_sizes, int n_in,
                              void* d_out, int out_size)
{
    const float* st    = (const float*)d_in[0];
    const float* lt    = (const float*)d_in[1];
    const float* w_st  = (const float*)d_in[2];
    const float* b_st  = (const float*)d_in[3];
    const float* w_lt  = (const float*)d_in[4];
    const float* b_lt  = (const float*)d_in[5];
    const float* w_g   = (const float*)d_in[6];
    const float* b_g   = (const float*)d_in[7];
    const float* ln_w  = (const float*)d_in[8];
    const float* ln_b  = (const float*)d_in[9];
    const float* w_out = (const float*)d_in[10];
    const float* b_out = (const float*)d_in[11];
    float* out = (float*)d_out;

    float *thetaT, *pg, *sc, *attnT, *nrmT, *lnTw, *lnTb, *stats;
    float *wstR, *wLG, *bLG, *woutR;
    float2 *part;
    cudaGetSymbolAddress((void**)&thetaT, g_thetaT);
    cudaGetSymbolAddress((void**)&pg,     g_pg);
    cudaGetSymbolAddress((void**)&sc,     g_sc);
    cudaGetSymbolAddress((void**)&attnT,  g_attnT);
    cudaGetSymbolAddress((void**)&nrmT,   g_nrmT);
    cudaGetSymbolAddress((void**)&lnTw,   g_lnTw);
    cudaGetSymbolAddress((void**)&lnTb,   g_lnTb);
    cudaGetSymbolAddress((void**)&part,   g_part);
    cudaGetSymbolAddress((void**)&stats,  g_stats);
    cudaGetSymbolAddress((void**)&wstR,   g_wstR);
    cudaGetSymbolAddress((void**)&wLG,    g_wLG);
    cudaGetSymbolAddress((void**)&bLG,    g_bLG);
    cudaGetSymbolAddress((void**)&woutR,  g_woutR);

    cudaFuncSetAttribute(gemm_mma<1,0,1,0>, cudaFuncAttributeMaxDynamicSharedMemorySize, GEMM_SMEM);
    cudaFuncSetAttribute(gemm_mma<0,0,0,0>, cudaFuncAttributeMaxDynamicSharedMemorySize, GEMM_SMEM);
    cudaFuncSetAttribute(gemm_big<1>, cudaFuncAttributeMaxDynamicSharedMemorySize, GEMM_BIG_SMEM);
    cudaFuncSetAttribute(gemm_big<0>, cudaFuncAttributeMaxDynamicSharedMemorySize, GEMM_BIG_SMEM);

    const float inv_sqrt_lat = 0.044194173824159216f;   // 1/sqrt(512)

    // fused pre-pass: 3 launches
    transpose2_kernel<<<dim3(S_ / 32, LAT_ / 32, 2), dim3(32, 8)>>>(ln_w, ln_b, lnTw, lnTb);
    round_copy4_kernel<<<4096, 256>>>(w_st, w_lt, w_g, w_out,
                                      wstR, wLG, wLG + (size_t)512 * C_LT_, woutR);
    stack_bias_kernel<<<4, 256>>>(b_lt, b_g, bLG);

    // 1) thetaT[s][o] = sum_c st[c][s] * w_st[o][c] + b_st[o]    (A transposed, round A)
    gemm_mma<1,0,1,0><<<dim3(LAT_ / 128, S_ / 128, NBATCH), 256, GEMM_SMEM>>>(
        st, wstR, thetaT, b_st, C_ST_, S_, C_ST_, LAT_,
        (size_t)C_ST_ * S_, 0, (size_t)S_ * LAT_, 1.f, 1, 1);

    // 2) merged phi+g (big-tile, cvt B): pg[o2][l] = sum_c wLG[o2][c] * lt[c][l] + bLG[o2]
    gemm_big<1><<<dim3(L_ / 256, 1024 / 128, NBATCH), 256, GEMM_BIG_SMEM>>>(
        wLG, lt, pg, bLG, C_LT_, C_LT_, L_, L_,
        0, (size_t)C_LT_ * L_, (size_t)1024 * L_, 1.f, 1);

    // 3) scores[s][l] = (1/sqrt(LAT)) * sum_o thetaT[s][o] * phi[o][l]  (big-tile, no cvt)
    gemm_big<0><<<dim3(L_ / 256, S_ / 128, NBATCH), 256, GEMM_BIG_SMEM>>>(
        thetaT, pg, sc, nullptr, LAT_, LAT_, L_, L_,
        (size_t)S_ * LAT_, (size_t)1024 * L_, (size_t)S_ * L_, inv_sqrt_lat, 0);

    // 4) softmax over L (in place, rounded output)
    softmax_kernel<<<NBATCH * S_, 256>>>(sc);

    // 5) attnT[s][c] = sum_l p[s][l] * g[c][l]
    gemm_mma<0,0,0,0><<<dim3(LAT_ / 128, S_ / 128, NBATCH), 256, GEMM_SMEM>>>(
        sc, pg + (size_t)512 * L_, attnT, nullptr, L_, L_, L_, LAT_,
        (size_t)S_ * L_, (size_t)1024 * L_, (size_t)S_ * LAT_, 1.f, 0, 0);

    // 6) layernorm stats (two-phase) + normalize + relu
    ln_part_kernel<<<dim3(16, NBATCH), 256>>>(attnT, part);
    ln_final_kernel<<<1, 32>>>(part, stats);
    norm_relu_kernel<<<(NBATCH * LAT_ * S_ / 4) / 256, 256>>>(attnT, lnTw, lnTb, stats, nrmT);

    // 7) out[o][s] = sum_c w_out[o][c] * nrmT[s][c] + b_out[o]
    gemm_mma<0,0,0,0><<<dim3(S_ / 128, C_ST_ / 128, NBATCH), 256, GEMM_SMEM>>>(
        woutR, nrmT, out, b_out, LAT_, LAT_, LAT_, S_,
        0, (size_t)S_ * LAT_, (size_t)C_ST_ * S_, 1.f, 2, 0);
}